// round 10
// baseline (speedup 1.0000x reference)
#include <cuda_runtime.h>
#include <cuda_bf16.h>
#include <cstdint>
#include <cstdio>

// Problem constants
#define BB 4
#define SS 2048
#define DD 1024
#define HH 16
#define DK 64
#define D3 3072
#define MM (BB*SS)          // 8192

// Scratch (device globals: allocation-free contract)
__device__ float g_qkv[(size_t)MM * D3];   // [B*S, 3D] : q | k | v
__device__ __nv_bfloat16 g_ahi[(size_t)MM * DD];
__device__ __nv_bfloat16 g_alo[(size_t)MM * DD];
__device__ __nv_bfloat16 g_bhi[(size_t)D3 * DD];
__device__ __nv_bfloat16 g_blo[(size_t)D3 * DD];
__device__ __nv_bfloat16 g_khi[(size_t)MM * DD];   // [b,h,s,dk]
__device__ __nv_bfloat16 g_klo[(size_t)MM * DD];
__device__ __nv_bfloat16 g_vthi[(size_t)MM * DD];  // [b,h,dk,s]
__device__ __nv_bfloat16 g_vtlo[(size_t)MM * DD];

// ---------------------------------------------------------------------------
// helpers
// ---------------------------------------------------------------------------
__device__ __forceinline__ uint32_t smem_u32(const void* p) {
    uint32_t a;
    asm("{ .reg .u64 t; cvta.to.shared.u64 t, %1; cvt.u32.u64 %0, t; }" : "=r"(a) : "l"(p));
    return a;
}
__device__ __forceinline__ void ldsm4(uint32_t& r0, uint32_t& r1, uint32_t& r2,
                                      uint32_t& r3, uint32_t addr) {
    asm volatile("ldmatrix.sync.aligned.m8n8.x4.shared.b16 {%0,%1,%2,%3}, [%4];"
                 : "=r"(r0), "=r"(r1), "=r"(r2), "=r"(r3) : "r"(addr));
}
__device__ __forceinline__ void mma16816(float* c, const uint32_t* a,
                                         uint32_t b0, uint32_t b1) {
    asm volatile(
        "mma.sync.aligned.m16n8k16.row.col.f32.bf16.bf16.f32 "
        "{%0,%1,%2,%3}, {%4,%5,%6,%7}, {%8,%9}, {%0,%1,%2,%3};"
        : "+f"(c[0]), "+f"(c[1]), "+f"(c[2]), "+f"(c[3])
        : "r"(a[0]), "r"(a[1]), "r"(a[2]), "r"(a[3]), "r"(b0), "r"(b1));
}
__device__ __forceinline__ uint32_t pack_bf2(float a, float b) {
    __nv_bfloat162 t = __floats2bfloat162_rn(a, b);
    return *(uint32_t*)&t;
}
__device__ __forceinline__ void cp16(uint32_t dst, const void* src) {
    asm volatile("cp.async.cg.shared.global [%0], [%1], 16;" :: "r"(dst), "l"(src));
}
#define CP_COMMIT() asm volatile("cp.async.commit_group;" ::: "memory")
#define CP_WAIT(n)  asm volatile("cp.async.wait_group %0;" :: "n"(n) : "memory")

// ---------------------------------------------------------------------------
// Split fp32 -> bf16 hi + bf16 lo (2 elements per thread)
// ---------------------------------------------------------------------------
__global__ __launch_bounds__(256) void split_bf16(const float2* __restrict__ x,
                                                  __nv_bfloat162* __restrict__ hi,
                                                  __nv_bfloat162* __restrict__ lo,
                                                  int n2) {
    int i = blockIdx.x * blockDim.x + threadIdx.x;
    if (i >= n2) return;
    float2 v = x[i];
    __nv_bfloat16 hx = __float2bfloat16(v.x);
    __nv_bfloat16 hy = __float2bfloat16(v.y);
    float rx = v.x - __bfloat162float(hx);
    float ry = v.y - __bfloat162float(hy);
    __nv_bfloat162 h; h.x = hx; h.y = hy;
    hi[i] = h;
    lo[i] = __floats2bfloat162_rn(rx, ry);
}

// ---------------------------------------------------------------------------
// Warp-MMA bf16 split-2 GEMM (NT): unchanged proven version.
// ---------------------------------------------------------------------------
#define RS 72
#define TILE_SMB (128 * RS * 2)
#define GEMM_SMEM (4 * TILE_SMB)

__global__ __launch_bounds__(256) void gemm_mma(
    const __nv_bfloat16* __restrict__ Ahi, const __nv_bfloat16* __restrict__ Alo,
    const __nv_bfloat16* __restrict__ Bhi, const __nv_bfloat16* __restrict__ Blo,
    float* __restrict__ C, int N, int K)
{
    extern __shared__ __align__(16) __nv_bfloat16 sm[];
    __nv_bfloat16* tile[4] = { sm, sm + 128 * RS, sm + 2 * 128 * RS, sm + 3 * 128 * RS };

    const int tid  = threadIdx.x;
    const int lane = tid & 31;
    const int wid  = tid >> 5;
    const int wm   = wid & 1;
    const int wn   = wid >> 1;
    const int m0 = blockIdx.y * 128;
    const int n0 = blockIdx.x * 128;

    const __nv_bfloat16* srcs[4] = { Ahi + (size_t)m0 * K, Alo + (size_t)m0 * K,
                                     Bhi + (size_t)n0 * K, Blo + (size_t)n0 * K };

    const int lrow  = (lane & 7) + ((lane >> 3) & 1) * 8;
    const int lkadd = (lane >> 4) * 8;

    const uint32_t smb = smem_u32(sm);
    const uint32_t aBaseHi = smb + (uint32_t)((wm * 64 + lrow) * RS + lkadd) * 2;
    const uint32_t aBaseLo = aBaseHi + TILE_SMB;
    const uint32_t bBaseHi = smb + 2 * TILE_SMB +
                             (uint32_t)((wn * 32 + lrow) * RS + lkadd) * 2;
    const uint32_t bBaseLo = bBaseHi + TILE_SMB;

    float acc[4][4][4];
#pragma unroll
    for (int i = 0; i < 4; i++)
#pragma unroll
        for (int j = 0; j < 4; j++)
#pragma unroll
            for (int r = 0; r < 4; r++) acc[i][j][r] = 0.0f;

    const int nStages = K >> 6;
    for (int s = 0; s < nStages; s++) {
        const int k0 = s << 6;
        __syncthreads();
#pragma unroll
        for (int t = 0; t < 4; t++) {
            const __nv_bfloat16* src = srcs[t] + k0;
#pragma unroll
            for (int it = 0; it < 4; it++) {
                int q = it * 256 + tid;
                int r = q >> 3;
                int c = q & 7;
                *(uint4*)(tile[t] + r * RS + c * 8) =
                    *(const uint4*)(src + (size_t)r * K + c * 8);
            }
        }
        __syncthreads();

#pragma unroll
        for (int ks = 0; ks < 4; ks++) {
            const uint32_t kb = (uint32_t)(ks * 16 * 2);
            uint32_t bH[8], bL[8];
            ldsm4(bH[0], bH[1], bH[2], bH[3], bBaseHi + kb);
            ldsm4(bH[4], bH[5], bH[6], bH[7], bBaseHi + kb + 16 * RS * 2);
            ldsm4(bL[0], bL[1], bL[2], bL[3], bBaseLo + kb);
            ldsm4(bL[4], bL[5], bL[6], bL[7], bBaseLo + kb + 16 * RS * 2);
#pragma unroll
            for (int mt = 0; mt < 4; mt++) {
                uint32_t aH[4], aL[4];
                const uint32_t moff = (uint32_t)(mt * 16 * RS * 2);
                ldsm4(aH[0], aH[1], aH[2], aH[3], aBaseHi + moff + kb);
                ldsm4(aL[0], aL[1], aL[2], aL[3], aBaseLo + moff + kb);
#pragma unroll
                for (int nt = 0; nt < 4; nt++) {
                    const int lo = ((nt >> 1) << 2) + (nt & 1);
                    mma16816(acc[mt][nt], aH, bH[lo], bH[lo + 2]);
                    mma16816(acc[mt][nt], aH, bL[lo], bL[lo + 2]);
                    mma16816(acc[mt][nt], aL, bH[lo], bH[lo + 2]);
                }
            }
        }
    }

    const int qrow = lane >> 2;
    const int qcol = (lane & 3) * 2;
#pragma unroll
    for (int mt = 0; mt < 4; mt++) {
#pragma unroll
        for (int nt = 0; nt < 4; nt++) {
            float* base = C + (size_t)(m0 + wm * 64 + mt * 16 + qrow) * N
                            + n0 + wn * 32 + nt * 8 + qcol;
            *(float2*)base = make_float2(acc[mt][nt][0], acc[mt][nt][1]);
            *(float2*)(base + (size_t)8 * N) = make_float2(acc[mt][nt][2], acc[mt][nt][3]);
        }
    }
}

// ---------------------------------------------------------------------------
// RoPE: q in-place (fp32); k -> rope'd, split to bf16 hi/lo in [b,h,s,dk].
// One thread per (b, s, h, pair j).
// ---------------------------------------------------------------------------
__global__ __launch_bounds__(256) void rope_split(float* __restrict__ qkv,
                                                  const int* __restrict__ pos,
                                                  __nv_bfloat16* __restrict__ khi,
                                                  __nv_bfloat16* __restrict__ klo) {
    int p = blockIdx.x * blockDim.x + threadIdx.x;
    if (p >= BB * SS * HH * (DK / 2)) return;
    int j = p & 31;
    int h = (p >> 5) & (HH - 1);
    int s = (p >> 9) & (SS - 1);
    int b = p >> 20;

    float e   = -(float)(2 * j) / (float)DK;
    float inv = powf(10000.0f, e);
    float ang = (float)pos[s] * inv;
    float sn, cs;
    sincosf(ang, &sn, &cs);

    size_t base = ((size_t)(b * SS + s)) * D3 + h * DK + 2 * j;
    float q1 = qkv[base], q2 = qkv[base + 1];
    qkv[base]     = q1 * cs - q2 * sn;
    qkv[base + 1] = q1 * sn + q2 * cs;

    float k1 = qkv[base + DD], k2 = qkv[base + DD + 1];
    float r1 = k1 * cs - k2 * sn;
    float r2 = k1 * sn + k2 * cs;
    __nv_bfloat16 h1 = __float2bfloat16(r1);
    __nv_bfloat16 h2 = __float2bfloat16(r2);
    size_t kdst = (((size_t)(b * HH + h) * SS + s)) * DK + 2 * j;
    __nv_bfloat162 hp; hp.x = h1; hp.y = h2;
    *(__nv_bfloat162*)(khi + kdst) = hp;
    *(__nv_bfloat162*)(klo + kdst) =
        __floats2bfloat162_rn(r1 - __bfloat162float(h1), r2 - __bfloat162float(h2));
}

// ---------------------------------------------------------------------------
// V: transpose + split -> vthi/vtlo [b,h,dk,S]. Tile 64s x 64d via smem.
// grid (SS/64, BB*HH), 256 threads.
// ---------------------------------------------------------------------------
__global__ __launch_bounds__(256) void splitv_t(const float* __restrict__ qkv,
                                                __nv_bfloat16* __restrict__ vthi,
                                                __nv_bfloat16* __restrict__ vtlo) {
    __shared__ float t[64][65];
    const int tid = threadIdx.x;
    const int s0 = blockIdx.x * 64;
    const int bh = blockIdx.y;
    const int b = bh >> 4, h = bh & 15;

#pragma unroll
    for (int it = 0; it < 4; it++) {
        int idx = it * 256 + tid;
        int sl = idx >> 4;
        int d4 = (idx & 15) * 4;
        float4 v = *(const float4*)(qkv + ((size_t)(b * SS + s0 + sl)) * D3
                                    + 2 * DD + h * DK + d4);
        t[sl][d4 + 0] = v.x; t[sl][d4 + 1] = v.y;
        t[sl][d4 + 2] = v.z; t[sl][d4 + 3] = v.w;
    }
    __syncthreads();

    const int d  = tid >> 2;
    const int sc = (tid & 3) * 16;
    __nv_bfloat16 hv[16], lv[16];
#pragma unroll
    for (int j = 0; j < 16; j++) {
        float v = t[sc + j][d];
        hv[j] = __float2bfloat16(v);
        lv[j] = __float2bfloat16(v - __bfloat162float(hv[j]));
    }
    size_t dst = ((size_t)(b * HH + h) * DK + d) * SS + s0 + sc;
    *(uint4*)(vthi + dst)     = *(uint4*)&hv[0];
    *(uint4*)(vthi + dst + 8) = *(uint4*)&hv[8];
    *(uint4*)(vtlo + dst)     = *(uint4*)&lv[0];
    *(uint4*)(vtlo + dst + 8) = *(uint4*)&lv[8];
}

// ---------------------------------------------------------------------------
// Tensor-core causal flash attention, cp.async double-buffered tiles.
// Stage = {Khi, Klo, Vthi, Vtlo} each [64][72] bf16 = 36864 B; 2 stages.
// Q staged through buffer 1 (fp32 load + split), fragments held in regs.
// Output written directly as bf16 hi/lo (A operand of out-proj).
// ---------------------------------------------------------------------------
#define ARS 72
#define STAGE_ELE (4 * 64 * ARS)            // 18432 bf16
#define ATTN_SMEM (2 * STAGE_ELE * 2)       // 73728 B

__device__ __forceinline__ void issue_stage(
    uint32_t sbase, const __nv_bfloat16* pKhi, const __nv_bfloat16* pKlo,
    const __nv_bfloat16* pVh, const __nv_bfloat16* pVl, int tid)
{
#pragma unroll
    for (int i = 0; i < 8; i++) {
        int chunk = i * 256 + tid;      // 2048 x 16B
        int t   = chunk >> 9;
        int c   = chunk & 511;
        int row = c >> 3, col = c & 7;
        uint32_t dst = sbase + (uint32_t)(t * 64 * ARS + row * ARS + col * 8) * 2;
        const __nv_bfloat16* src;
        if (t == 0)      src = pKhi + c * 8;            // contiguous tile
        else if (t == 1) src = pKlo + c * 8;
        else if (t == 2) src = pVh + (size_t)row * SS + col * 8;
        else             src = pVl + (size_t)row * SS + col * 8;
        cp16(dst, src);
    }
}

__global__ __launch_bounds__(256) void attn_mma(
    const float* __restrict__ qkv,
    const __nv_bfloat16* __restrict__ khi, const __nv_bfloat16* __restrict__ klo,
    const __nv_bfloat16* __restrict__ vthi, const __nv_bfloat16* __restrict__ vtlo,
    __nv_bfloat16* __restrict__ ohi, __nv_bfloat16* __restrict__ olo)
{
    extern __shared__ __align__(16) __nv_bfloat16 as_[];
    __nv_bfloat16* buf0 = as_;
    __nv_bfloat16* buf1 = as_ + STAGE_ELE;

    const int tid  = threadIdx.x;
    const int lane = tid & 31;
    const int wid  = tid >> 5;
    const int qb = blockIdx.x;
    const int h  = blockIdx.y;
    const int b  = blockIdx.z;

    // ---- load Q (scaled 1/8) into buf1 as hi/lo ----
    __nv_bfloat16* Qhi = buf1;
    __nv_bfloat16* Qlo = buf1 + 128 * ARS;
#pragma unroll
    for (int it = 0; it < 8; it++) {
        int idx = it * 256 + tid;
        int r = idx >> 4;
        int c = (idx & 15) * 4;
        const float* src = qkv + ((size_t)(b * SS + qb * 128 + r)) * D3 + h * DK + c;
        float4 v = *(const float4*)src;
        float f[4] = { v.x * 0.125f, v.y * 0.125f, v.z * 0.125f, v.w * 0.125f };
        __nv_bfloat16 hh[4]; float ll[4];
#pragma unroll
        for (int i = 0; i < 4; i++) { hh[i] = __float2bfloat16(f[i]);
                                      ll[i] = f[i] - __bfloat162float(hh[i]); }
        __nv_bfloat162 p0; p0.x = hh[0]; p0.y = hh[1];
        __nv_bfloat162 p1; p1.x = hh[2]; p1.y = hh[3];
        *(__nv_bfloat162*)(Qhi + r * ARS + c)     = p0;
        *(__nv_bfloat162*)(Qhi + r * ARS + c + 2) = p1;
        *(__nv_bfloat162*)(Qlo + r * ARS + c)     = __floats2bfloat162_rn(ll[0], ll[1]);
        *(__nv_bfloat162*)(Qlo + r * ARS + c + 2) = __floats2bfloat162_rn(ll[2], ll[3]);
    }
    __syncthreads();

    // ---- Q fragments in registers ----
    const int lrow  = (lane & 7) + ((lane >> 3) & 1) * 8;
    const int lkadd = (lane >> 4) * 8;
    const uint32_t qBaseHi = smem_u32(Qhi) + (uint32_t)((wid * 16 + lrow) * ARS + lkadd) * 2;
    const uint32_t qBaseLo = smem_u32(Qlo) + (uint32_t)((wid * 16 + lrow) * ARS + lkadd) * 2;
    uint32_t qh[4][4], ql[4][4];
#pragma unroll
    for (int kc = 0; kc < 4; kc++) {
        ldsm4(qh[kc][0], qh[kc][1], qh[kc][2], qh[kc][3], qBaseHi + kc * 32);
        ldsm4(ql[kc][0], ql[kc][1], ql[kc][2], ql[kc][3], qBaseLo + kc * 32);
    }
    __syncthreads();   // all warps done reading Q before buf1 is reused

    // gmem tile base pointers (per b,h)
    const size_t kvbase = (size_t)(b * HH + h) * SS * DK;
    const __nv_bfloat16* pKhi0 = khi  + kvbase;
    const __nv_bfloat16* pKlo0 = klo  + kvbase;
    const __nv_bfloat16* pVh0  = vthi + kvbase;   // [dk][S]
    const __nv_bfloat16* pVl0  = vtlo + kvbase;

    const uint32_t sb[2] = { smem_u32(buf0), smem_u32(buf1) };
    const uint32_t fragOff  = (uint32_t)(lrow * ARS + lkadd) * 2;

    float oacc[8][4];
#pragma unroll
    for (int nt = 0; nt < 8; nt++)
#pragma unroll
        for (int r = 0; r < 4; r++) oacc[nt][r] = 0.0f;
    float m0 = -1e30f, m1 = -1e30f, l0 = 0.0f, l1 = 0.0f;

    const int grow0 = qb * 128 + wid * 16 + (lane >> 2);
    const int grow1 = grow0 + 8;
    const int nkt = 2 * qb + 2;

    // prologue: stage 0 -> buf0
    issue_stage(sb[0], pKhi0, pKlo0, pVh0, pVl0, tid);
    CP_COMMIT();

    for (int kt = 0; kt < nkt; kt++) {
        if (kt + 1 < nkt) {
            int o = (kt + 1) * 64;
            issue_stage(sb[(kt + 1) & 1], pKhi0 + o * DK, pKlo0 + o * DK,
                        pVh0 + o, pVl0 + o, tid);
            CP_COMMIT();
            CP_WAIT(1);
        } else {
            CP_WAIT(0);
        }
        __syncthreads();

        const uint32_t cur = sb[kt & 1];
        const uint32_t kBaseHi = cur + fragOff;
        const uint32_t kBaseLo = cur + (uint32_t)(64 * ARS * 2) + fragOff;
        const uint32_t vBaseHi = cur + (uint32_t)(2 * 64 * ARS * 2) + fragOff;
        const uint32_t vBaseLo = cur + (uint32_t)(3 * 64 * ARS * 2) + fragOff;

        // ---- S = Q K^T (split-2, 3 passes) ----
        float sacc[8][4];
#pragma unroll
        for (int nt = 0; nt < 8; nt++)
#pragma unroll
            for (int r = 0; r < 4; r++) sacc[nt][r] = 0.0f;

#pragma unroll
        for (int kc = 0; kc < 4; kc++) {
            const uint32_t kb = (uint32_t)(kc * 32);
            uint32_t bH[16], bL[16];
#pragma unroll
            for (int lb = 0; lb < 4; lb++) {
                ldsm4(bH[lb * 4 + 0], bH[lb * 4 + 1], bH[lb * 4 + 2], bH[lb * 4 + 3],
                      kBaseHi + kb + (uint32_t)(lb * 16 * ARS * 2));
                ldsm4(bL[lb * 4 + 0], bL[lb * 4 + 1], bL[lb * 4 + 2], bL[lb * 4 + 3],
                      kBaseLo + kb + (uint32_t)(lb * 16 * ARS * 2));
            }
#pragma unroll
            for (int nt = 0; nt < 8; nt++) {
                const int lo = ((nt >> 1) << 2) + (nt & 1);
                mma16816(sacc[nt], qh[kc], bH[lo], bH[lo + 2]);
                mma16816(sacc[nt], qh[kc], bL[lo], bL[lo + 2]);
                mma16816(sacc[nt], ql[kc], bH[lo], bH[lo + 2]);
            }
        }

        // ---- causal mask ----
        if (kt * 64 + 63 > qb * 128 + wid * 16) {
#pragma unroll
            for (int nt = 0; nt < 8; nt++) {
                int col = kt * 64 + nt * 8 + (lane & 3) * 2;
                if (col > grow0)     sacc[nt][0] = -1e30f;
                if (col + 1 > grow0) sacc[nt][1] = -1e30f;
                if (col > grow1)     sacc[nt][2] = -1e30f;
                if (col + 1 > grow1) sacc[nt][3] = -1e30f;
            }
        }

        // ---- online softmax ----
        float mx0 = -1e30f, mx1 = -1e30f;
#pragma unroll
        for (int nt = 0; nt < 8; nt++) {
            mx0 = fmaxf(mx0, fmaxf(sacc[nt][0], sacc[nt][1]));
            mx1 = fmaxf(mx1, fmaxf(sacc[nt][2], sacc[nt][3]));
        }
        mx0 = fmaxf(mx0, __shfl_xor_sync(0xffffffffu, mx0, 1));
        mx0 = fmaxf(mx0, __shfl_xor_sync(0xffffffffu, mx0, 2));
        mx1 = fmaxf(mx1, __shfl_xor_sync(0xffffffffu, mx1, 1));
        mx1 = fmaxf(mx1, __shfl_xor_sync(0xffffffffu, mx1, 2));
        float mn0 = fmaxf(m0, mx0), mn1 = fmaxf(m1, mx1);
        float cr0 = __expf(m0 - mn0), cr1 = __expf(m1 - mn1);
        float ps0 = 0.0f, ps1 = 0.0f;
#pragma unroll
        for (int nt = 0; nt < 8; nt++) {
            sacc[nt][0] = __expf(sacc[nt][0] - mn0);
            sacc[nt][1] = __expf(sacc[nt][1] - mn0);
            sacc[nt][2] = __expf(sacc[nt][2] - mn1);
            sacc[nt][3] = __expf(sacc[nt][3] - mn1);
            ps0 += sacc[nt][0] + sacc[nt][1];
            ps1 += sacc[nt][2] + sacc[nt][3];
        }
        ps0 += __shfl_xor_sync(0xffffffffu, ps0, 1);
        ps0 += __shfl_xor_sync(0xffffffffu, ps0, 2);
        ps1 += __shfl_xor_sync(0xffffffffu, ps1, 1);
        ps1 += __shfl_xor_sync(0xffffffffu, ps1, 2);
        l0 = l0 * cr0 + ps0;
        l1 = l1 * cr1 + ps1;
        m0 = mn0; m1 = mn1;
#pragma unroll
        for (int nt = 0; nt < 8; nt++) {
            oacc[nt][0] *= cr0; oacc[nt][1] *= cr0;
            oacc[nt][2] *= cr1; oacc[nt][3] *= cr1;
        }

        // ---- O += P V (split-2, 3 passes) ----
#pragma unroll
        for (int kc = 0; kc < 4; kc++) {
            float f00 = sacc[2*kc][0],   f01 = sacc[2*kc][1];
            float f02 = sacc[2*kc][2],   f03 = sacc[2*kc][3];
            float f10 = sacc[2*kc+1][0], f11 = sacc[2*kc+1][1];
            float f12 = sacc[2*kc+1][2], f13 = sacc[2*kc+1][3];
            __nv_bfloat16 h00 = __float2bfloat16(f00), h01 = __float2bfloat16(f01);
            __nv_bfloat16 h02 = __float2bfloat16(f02), h03 = __float2bfloat16(f03);
            __nv_bfloat16 h10 = __float2bfloat16(f10), h11 = __float2bfloat16(f11);
            __nv_bfloat16 h12 = __float2bfloat16(f12), h13 = __float2bfloat16(f13);
            uint32_t aH[4], aL[4];
            { __nv_bfloat162 t; t.x=h00; t.y=h01; aH[0]=*(uint32_t*)&t; }
            { __nv_bfloat162 t; t.x=h02; t.y=h03; aH[1]=*(uint32_t*)&t; }
            { __nv_bfloat162 t; t.x=h10; t.y=h11; aH[2]=*(uint32_t*)&t; }
            { __nv_bfloat162 t; t.x=h12; t.y=h13; aH[3]=*(uint32_t*)&t; }
            aL[0] = pack_bf2(f00 - __bfloat162float(h00), f01 - __bfloat162float(h01));
            aL[1] = pack_bf2(f02 - __bfloat162float(h02), f03 - __bfloat162float(h03));
            aL[2] = pack_bf2(f10 - __bfloat162float(h10), f11 - __bfloat162float(h11));
            aL[3] = pack_bf2(f12 - __bfloat162float(h12), f13 - __bfloat162float(h13));

            const uint32_t kb = (uint32_t)(kc * 32);
            uint32_t vH[16], vL[16];
#pragma unroll
            for (int lb = 0; lb < 4; lb++) {
                ldsm4(vH[lb * 4 + 0], vH[lb * 4 + 1], vH[lb * 4 + 2], vH[lb * 4 + 3],
                      vBaseHi + kb + (uint32_t)(lb * 16 * ARS * 2));
                ldsm4(vL[lb * 4 + 0], vL[lb * 4 + 1], vL[lb * 4 + 2], vL[lb * 4 + 3],
                      vBaseLo + kb + (uint32_t)(lb * 16 * ARS * 2));
            }
#pragma unroll
            for (int nt = 0; nt < 8; nt++) {
                const int lo = ((nt >> 1) << 2) + (nt & 1);
                mma16816(oacc[nt], aH, vH[lo], vH[lo + 2]);
                mma16816(oacc[nt], aH, vL[lo], vL[lo + 2]);
                mma16816(oacc[nt], aL, vH[lo], vH[lo + 2]);
            }
        }
        __syncthreads();   // all reads of cur done before it is overwritten
    }

    // ---- epilogue: write output as bf16 hi/lo ----
    const float inv0 = 1.0f / l0;
    const float inv1 = 1.0f / l1;
    const int row0 = qb * 128 + wid * 16 + (lane >> 2);
#pragma unroll
    for (int nt = 0; nt < 8; nt++) {
        int col = h * DK + nt * 8 + (lane & 3) * 2;
        size_t d0 = ((size_t)(b * SS + row0)) * DD + col;
        size_t d1 = d0 + (size_t)8 * DD;
        float v00 = oacc[nt][0] * inv0, v01 = oacc[nt][1] * inv0;
        float v10 = oacc[nt][2] * inv1, v11 = oacc[nt][3] * inv1;
        __nv_bfloat16 a = __float2bfloat16(v00), c = __float2bfloat16(v01);
        __nv_bfloat16 d = __float2bfloat16(v10), e = __float2bfloat16(v11);
        { __nv_bfloat162 t; t.x = a; t.y = c; *(__nv_bfloat162*)(ohi + d0) = t; }
        { __nv_bfloat162 t; t.x = d; t.y = e; *(__nv_bfloat162*)(ohi + d1) = t; }
        *(__nv_bfloat162*)(olo + d0) =
            __floats2bfloat162_rn(v00 - __bfloat162float(a), v01 - __bfloat162float(c));
        *(__nv_bfloat162*)(olo + d1) =
            __floats2bfloat162_rn(v10 - __bfloat162float(d), v11 - __bfloat162float(e));
    }
}

// ---------------------------------------------------------------------------
extern "C" void kernel_launch(void* const* d_in, const int* in_sizes, int n_in,
                              void* d_out, int out_size) {
    const float* x    = (const float*)d_in[0];
    const int*   pos  = (const int*)d_in[1];
    const float* Wqkv = (const float*)d_in[2];
    const float* Wo   = (const float*)d_in[3];
    float* out = (float*)d_out;

    float *qkv = nullptr;
    __nv_bfloat16 *ahi, *alo, *bhi, *blo, *khi, *klo, *vthi, *vtlo;
    cudaGetSymbolAddress((void**)&qkv, g_qkv);
    cudaGetSymbolAddress((void**)&ahi, g_ahi);
    cudaGetSymbolAddress((void**)&alo, g_alo);
    cudaGetSymbolAddress((void**)&bhi, g_bhi);
    cudaGetSymbolAddress((void**)&blo, g_blo);
    cudaGetSymbolAddress((void**)&khi, g_khi);
    cudaGetSymbolAddress((void**)&klo, g_klo);
    cudaGetSymbolAddress((void**)&vthi, g_vthi);
    cudaGetSymbolAddress((void**)&vtlo, g_vtlo);

    cudaFuncSetAttribute(gemm_mma, cudaFuncAttributeMaxDynamicSharedMemorySize, GEMM_SMEM);
    cudaFuncSetAttribute(attn_mma, cudaFuncAttributeMaxDynamicSharedMemorySize, ATTN_SMEM);

    // 1) split x and Wqkv to bf16 hi/lo
    {
        int n2 = MM * DD / 2;
        split_bf16<<<(n2 + 255) / 256, 256>>>((const float2*)x,
            (__nv_bfloat162*)ahi, (__nv_bfloat162*)alo, n2);
        int w2 = D3 * DD / 2;
        split_bf16<<<(w2 + 255) / 256, 256>>>((const float2*)Wqkv,
            (__nv_bfloat162*)bhi, (__nv_bfloat162*)blo, w2);
    }

    // 2) QKV projection: [8192,1024] x [3072,1024]^T
    {
        dim3 grid(D3 / 128, MM / 128);
        gemm_mma<<<grid, 256, GEMM_SMEM>>>(ahi, alo, bhi, blo, qkv, D3, DD);
    }

    // 3) RoPE (q in place, k split to bf16) + V transpose-split
    {
        int total = BB * SS * HH * (DK / 2);
        rope_split<<<(total + 255) / 256, 256>>>(qkv, pos, khi, klo);
        dim3 gv(SS / 64, BB * HH);
        splitv_t<<<gv, 256>>>(qkv, vthi, vtlo);
    }

    // 4) Causal flash attention (tensor cores, cp.async pipelined);
    //    writes output directly as bf16 hi/lo into ahi/alo
    {
        dim3 grid(SS / 128, HH, BB);
        attn_mma<<<grid, 256, ATTN_SMEM>>>(qkv, khi, klo, vthi, vtlo, ahi, alo);
    }

    // 5) split Wo, then output projection to fp32 out
    {
        int w2 = DD * DD / 2;
        split_bf16<<<(w2 + 255) / 256, 256>>>((const float2*)Wo,
            (__nv_bfloat162*)bhi, (__nv_bfloat162*)blo, w2);
        dim3 grid(DD / 128, MM / 128);
        gemm_mma<<<grid, 256, GEMM_SMEM>>>(ahi, alo, bhi, blo, out, DD, DD);
    }
}

// round 12
// speedup vs baseline: 1.1017x; 1.1017x over previous
#include <cuda_runtime.h>
#include <cuda_bf16.h>
#include <cstdint>
#include <cstdio>

// Problem constants
#define BB 4
#define SS 2048
#define DD 1024
#define HH 16
#define DK 64
#define D3 3072
#define MM (BB*SS)          // 8192

// Scratch (device globals: allocation-free contract)
__device__ float g_qkv[(size_t)MM * D3];   // [B*S, 3D] : q | k | v
__device__ __nv_bfloat16 g_ahi[(size_t)MM * DD];
__device__ __nv_bfloat16 g_alo[(size_t)MM * DD];
__device__ __nv_bfloat16 g_bhi[(size_t)D3 * DD];
__device__ __nv_bfloat16 g_blo[(size_t)D3 * DD];
__device__ __nv_bfloat16 g_khi[(size_t)MM * DD];   // [b,h,s,dk]
__device__ __nv_bfloat16 g_klo[(size_t)MM * DD];
__device__ __nv_bfloat16 g_vthi[(size_t)MM * DD];  // [b,h,dk,s]
__device__ __nv_bfloat16 g_vtlo[(size_t)MM * DD];

// ---------------------------------------------------------------------------
// helpers
// ---------------------------------------------------------------------------
__device__ __forceinline__ uint32_t smem_u32(const void* p) {
    uint32_t a;
    asm("{ .reg .u64 t; cvta.to.shared.u64 t, %1; cvt.u32.u64 %0, t; }" : "=r"(a) : "l"(p));
    return a;
}
__device__ __forceinline__ void ldsm4(uint32_t& r0, uint32_t& r1, uint32_t& r2,
                                      uint32_t& r3, uint32_t addr) {
    asm volatile("ldmatrix.sync.aligned.m8n8.x4.shared.b16 {%0,%1,%2,%3}, [%4];"
                 : "=r"(r0), "=r"(r1), "=r"(r2), "=r"(r3) : "r"(addr));
}
__device__ __forceinline__ void mma16816(float* c, const uint32_t* a,
                                         uint32_t b0, uint32_t b1) {
    asm volatile(
        "mma.sync.aligned.m16n8k16.row.col.f32.bf16.bf16.f32 "
        "{%0,%1,%2,%3}, {%4,%5,%6,%7}, {%8,%9}, {%0,%1,%2,%3};"
        : "+f"(c[0]), "+f"(c[1]), "+f"(c[2]), "+f"(c[3])
        : "r"(a[0]), "r"(a[1]), "r"(a[2]), "r"(a[3]), "r"(b0), "r"(b1));
}
__device__ __forceinline__ uint32_t pack_bf2(float a, float b) {
    __nv_bfloat162 t = __floats2bfloat162_rn(a, b);
    return *(uint32_t*)&t;
}
__device__ __forceinline__ void cp16(uint32_t dst, const void* src) {
    asm volatile("cp.async.cg.shared.global [%0], [%1], 16;" :: "r"(dst), "l"(src));
}
#define CP_COMMIT() asm volatile("cp.async.commit_group;" ::: "memory")
#define CP_WAIT(n)  asm volatile("cp.async.wait_group %0;" :: "n"(n) : "memory")

// ---------------------------------------------------------------------------
// Split fp32 -> bf16 hi + bf16 lo (2 elements per thread)
// ---------------------------------------------------------------------------
__global__ __launch_bounds__(256) void split_bf16(const float2* __restrict__ x,
                                                  __nv_bfloat162* __restrict__ hi,
                                                  __nv_bfloat162* __restrict__ lo,
                                                  int n2) {
    int i = blockIdx.x * blockDim.x + threadIdx.x;
    if (i >= n2) return;
    float2 v = x[i];
    __nv_bfloat16 hx = __float2bfloat16(v.x);
    __nv_bfloat16 hy = __float2bfloat16(v.y);
    float rx = v.x - __bfloat162float(hx);
    float ry = v.y - __bfloat162float(hy);
    __nv_bfloat162 h; h.x = hx; h.y = hy;
    hi[i] = h;
    lo[i] = __floats2bfloat162_rn(rx, ry);
}

// ---------------------------------------------------------------------------
// Warp-MMA bf16 split-2 GEMM (NT), cp.async double-buffered.
// CTA tile 128x128, KBLK=64. 8 warps: 2(M) x 4(N), warp tile 64x32.
// smem: 2 stages x 4 tiles x [128][72] bf16 = 147456 B  -> 1 CTA/SM.
// C += Ahi Bhi^T + Ahi Blo^T + Alo Bhi^T
// ---------------------------------------------------------------------------
#define RS 72
#define TILE_SMB (128 * RS * 2)             // 18432 B per tile
#define GSTAGE_ELE (4 * 128 * RS)           // bf16 per stage
#define GEMM_SMEM (2 * GSTAGE_ELE * 2)      // 147456 B

__device__ __forceinline__ void gemm_issue_stage(
    uint32_t sbase, const __nv_bfloat16* const* srcs, int k0, int K, int tid)
{
#pragma unroll
    for (int t = 0; t < 4; t++) {
        const __nv_bfloat16* src = srcs[t] + k0;
#pragma unroll
        for (int it = 0; it < 4; it++) {
            int q = it * 256 + tid;          // 0..1023 16B-chunks
            int r = q >> 3;
            int c = q & 7;
            cp16(sbase + (uint32_t)(t * 128 * RS + r * RS + c * 8) * 2,
                 src + (size_t)r * K + c * 8);
        }
    }
}

__global__ __launch_bounds__(256) void gemm_mma(
    const __nv_bfloat16* __restrict__ Ahi, const __nv_bfloat16* __restrict__ Alo,
    const __nv_bfloat16* __restrict__ Bhi, const __nv_bfloat16* __restrict__ Blo,
    float* __restrict__ C, int N, int K)
{
    extern __shared__ __align__(16) __nv_bfloat16 sm[];

    const int tid  = threadIdx.x;
    const int lane = tid & 31;
    const int wid  = tid >> 5;
    const int wm   = wid & 1;
    const int wn   = wid >> 1;
    const int m0 = blockIdx.y * 128;
    const int n0 = blockIdx.x * 128;

    const __nv_bfloat16* srcs[4] = { Ahi + (size_t)m0 * K, Alo + (size_t)m0 * K,
                                     Bhi + (size_t)n0 * K, Blo + (size_t)n0 * K };

    const int lrow  = (lane & 7) + ((lane >> 3) & 1) * 8;
    const int lkadd = (lane >> 4) * 8;

    const uint32_t sb[2] = { smem_u32(sm), smem_u32(sm + GSTAGE_ELE) };
    const uint32_t aOffHi = (uint32_t)((wm * 64 + lrow) * RS + lkadd) * 2;
    const uint32_t aOffLo = aOffHi + TILE_SMB;
    const uint32_t bOffHi = 2 * TILE_SMB + (uint32_t)((wn * 32 + lrow) * RS + lkadd) * 2;
    const uint32_t bOffLo = bOffHi + TILE_SMB;

    float acc[4][4][4];
#pragma unroll
    for (int i = 0; i < 4; i++)
#pragma unroll
        for (int j = 0; j < 4; j++)
#pragma unroll
            for (int r = 0; r < 4; r++) acc[i][j][r] = 0.0f;

    const int nStages = K >> 6;

    // prologue
    gemm_issue_stage(sb[0], srcs, 0, K, tid);
    CP_COMMIT();

    for (int s = 0; s < nStages; s++) {
        if (s + 1 < nStages) {
            gemm_issue_stage(sb[(s + 1) & 1], srcs, (s + 1) << 6, K, tid);
            CP_COMMIT();
            CP_WAIT(1);
        } else {
            CP_WAIT(0);
        }
        __syncthreads();

        const uint32_t cur = sb[s & 1];
        const uint32_t aBaseHi = cur + aOffHi;
        const uint32_t aBaseLo = cur + aOffLo;
        const uint32_t bBaseHi = cur + bOffHi;
        const uint32_t bBaseLo = cur + bOffLo;

#pragma unroll
        for (int ks = 0; ks < 4; ks++) {
            const uint32_t kb = (uint32_t)(ks * 16 * 2);
            uint32_t bH[8], bL[8];
            ldsm4(bH[0], bH[1], bH[2], bH[3], bBaseHi + kb);
            ldsm4(bH[4], bH[5], bH[6], bH[7], bBaseHi + kb + 16 * RS * 2);
            ldsm4(bL[0], bL[1], bL[2], bL[3], bBaseLo + kb);
            ldsm4(bL[4], bL[5], bL[6], bL[7], bBaseLo + kb + 16 * RS * 2);
#pragma unroll
            for (int mt = 0; mt < 4; mt++) {
                uint32_t aH[4], aL[4];
                const uint32_t moff = (uint32_t)(mt * 16 * RS * 2);
                ldsm4(aH[0], aH[1], aH[2], aH[3], aBaseHi + moff + kb);
                ldsm4(aL[0], aL[1], aL[2], aL[3], aBaseLo + moff + kb);
#pragma unroll
                for (int nt = 0; nt < 4; nt++) {
                    const int lo = ((nt >> 1) << 2) + (nt & 1);
                    mma16816(acc[mt][nt], aH, bH[lo], bH[lo + 2]);
                    mma16816(acc[mt][nt], aH, bL[lo], bL[lo + 2]);
                    mma16816(acc[mt][nt], aL, bH[lo], bH[lo + 2]);
                }
            }
        }
        __syncthreads();
    }

    const int qrow = lane >> 2;
    const int qcol = (lane & 3) * 2;
#pragma unroll
    for (int mt = 0; mt < 4; mt++) {
#pragma unroll
        for (int nt = 0; nt < 4; nt++) {
            float* base = C + (size_t)(m0 + wm * 64 + mt * 16 + qrow) * N
                            + n0 + wn * 32 + nt * 8 + qcol;
            *(float2*)base = make_float2(acc[mt][nt][0], acc[mt][nt][1]);
            *(float2*)(base + (size_t)8 * N) = make_float2(acc[mt][nt][2], acc[mt][nt][3]);
        }
    }
}

// ---------------------------------------------------------------------------
// RoPE: q in-place (fp32); k -> rope'd, split to bf16 hi/lo in [b,h,s,dk].
// ---------------------------------------------------------------------------
__global__ __launch_bounds__(256) void rope_split(float* __restrict__ qkv,
                                                  const int* __restrict__ pos,
                                                  __nv_bfloat16* __restrict__ khi,
                                                  __nv_bfloat16* __restrict__ klo) {
    int p = blockIdx.x * blockDim.x + threadIdx.x;
    if (p >= BB * SS * HH * (DK / 2)) return;
    int j = p & 31;
    int h = (p >> 5) & (HH - 1);
    int s = (p >> 9) & (SS - 1);
    int b = p >> 20;

    float e   = -(float)(2 * j) / (float)DK;
    float inv = powf(10000.0f, e);
    float ang = (float)pos[s] * inv;
    float sn, cs;
    sincosf(ang, &sn, &cs);

    size_t base = ((size_t)(b * SS + s)) * D3 + h * DK + 2 * j;
    float q1 = qkv[base], q2 = qkv[base + 1];
    qkv[base]     = q1 * cs - q2 * sn;
    qkv[base + 1] = q1 * sn + q2 * cs;

    float k1 = qkv[base + DD], k2 = qkv[base + DD + 1];
    float r1 = k1 * cs - k2 * sn;
    float r2 = k1 * sn + k2 * cs;
    __nv_bfloat16 h1 = __float2bfloat16(r1);
    __nv_bfloat16 h2 = __float2bfloat16(r2);
    size_t kdst = (((size_t)(b * HH + h) * SS + s)) * DK + 2 * j;
    __nv_bfloat162 hp; hp.x = h1; hp.y = h2;
    *(__nv_bfloat162*)(khi + kdst) = hp;
    *(__nv_bfloat162*)(klo + kdst) =
        __floats2bfloat162_rn(r1 - __bfloat162float(h1), r2 - __bfloat162float(h2));
}

// ---------------------------------------------------------------------------
// V: transpose + split -> vthi/vtlo [b,h,dk,S]. Tile 64s x 64d via smem.
// ---------------------------------------------------------------------------
__global__ __launch_bounds__(256) void splitv_t(const float* __restrict__ qkv,
                                                __nv_bfloat16* __restrict__ vthi,
                                                __nv_bfloat16* __restrict__ vtlo) {
    __shared__ float t[64][65];
    const int tid = threadIdx.x;
    const int s0 = blockIdx.x * 64;
    const int bh = blockIdx.y;
    const int b = bh >> 4, h = bh & 15;

#pragma unroll
    for (int it = 0; it < 4; it++) {
        int idx = it * 256 + tid;
        int sl = idx >> 4;
        int d4 = (idx & 15) * 4;
        float4 v = *(const float4*)(qkv + ((size_t)(b * SS + s0 + sl)) * D3
                                    + 2 * DD + h * DK + d4);
        t[sl][d4 + 0] = v.x; t[sl][d4 + 1] = v.y;
        t[sl][d4 + 2] = v.z; t[sl][d4 + 3] = v.w;
    }
    __syncthreads();

    const int d  = tid >> 2;
    const int sc = (tid & 3) * 16;
    __nv_bfloat16 hv[16], lv[16];
#pragma unroll
    for (int j = 0; j < 16; j++) {
        float v = t[sc + j][d];
        hv[j] = __float2bfloat16(v);
        lv[j] = __float2bfloat16(v - __bfloat162float(hv[j]));
    }
    size_t dst = ((size_t)(b * HH + h) * DK + d) * SS + s0 + sc;
    *(uint4*)(vthi + dst)     = *(uint4*)&hv[0];
    *(uint4*)(vthi + dst + 8) = *(uint4*)&hv[8];
    *(uint4*)(vtlo + dst)     = *(uint4*)&lv[0];
    *(uint4*)(vtlo + dst + 8) = *(uint4*)&lv[8];
}

// ---------------------------------------------------------------------------
// Tensor-core causal flash attention, cp.async double-buffered (unchanged).
// ---------------------------------------------------------------------------
#define ARS 72
#define STAGE_ELE (4 * 64 * ARS)            // 18432 bf16
#define ATTN_SMEM (2 * STAGE_ELE * 2)       // 73728 B

__device__ __forceinline__ void issue_stage(
    uint32_t sbase, const __nv_bfloat16* pKhi, const __nv_bfloat16* pKlo,
    const __nv_bfloat16* pVh, const __nv_bfloat16* pVl, int tid)
{
#pragma unroll
    for (int i = 0; i < 8; i++) {
        int chunk = i * 256 + tid;      // 2048 x 16B
        int t   = chunk >> 9;
        int c   = chunk & 511;
        int row = c >> 3, col = c & 7;
        uint32_t dst = sbase + (uint32_t)(t * 64 * ARS + row * ARS + col * 8) * 2;
        const __nv_bfloat16* src;
        if (t == 0)      src = pKhi + c * 8;
        else if (t == 1) src = pKlo + c * 8;
        else if (t == 2) src = pVh + (size_t)row * SS + col * 8;
        else             src = pVl + (size_t)row * SS + col * 8;
        cp16(dst, src);
    }
}

__global__ __launch_bounds__(256) void attn_mma(
    const float* __restrict__ qkv,
    const __nv_bfloat16* __restrict__ khi, const __nv_bfloat16* __restrict__ klo,
    const __nv_bfloat16* __restrict__ vthi, const __nv_bfloat16* __restrict__ vtlo,
    __nv_bfloat16* __restrict__ ohi, __nv_bfloat16* __restrict__ olo)
{
    extern __shared__ __align__(16) __nv_bfloat16 as_[];
    __nv_bfloat16* buf0 = as_;
    __nv_bfloat16* buf1 = as_ + STAGE_ELE;

    const int tid  = threadIdx.x;
    const int lane = tid & 31;
    const int wid  = tid >> 5;
    const int qb = blockIdx.x;
    const int h  = blockIdx.y;
    const int b  = blockIdx.z;

    // ---- load Q (scaled 1/8) into buf1 as hi/lo ----
    __nv_bfloat16* Qhi = buf1;
    __nv_bfloat16* Qlo = buf1 + 128 * ARS;
#pragma unroll
    for (int it = 0; it < 8; it++) {
        int idx = it * 256 + tid;
        int r = idx >> 4;
        int c = (idx & 15) * 4;
        const float* src = qkv + ((size_t)(b * SS + qb * 128 + r)) * D3 + h * DK + c;
        float4 v = *(const float4*)src;
        float f[4] = { v.x * 0.125f, v.y * 0.125f, v.z * 0.125f, v.w * 0.125f };
        __nv_bfloat16 hh[4]; float ll[4];
#pragma unroll
        for (int i = 0; i < 4; i++) { hh[i] = __float2bfloat16(f[i]);
                                      ll[i] = f[i] - __bfloat162float(hh[i]); }
        __nv_bfloat162 p0; p0.x = hh[0]; p0.y = hh[1];
        __nv_bfloat162 p1; p1.x = hh[2]; p1.y = hh[3];
        *(__nv_bfloat162*)(Qhi + r * ARS + c)     = p0;
        *(__nv_bfloat162*)(Qhi + r * ARS + c + 2) = p1;
        *(__nv_bfloat162*)(Qlo + r * ARS + c)     = __floats2bfloat162_rn(ll[0], ll[1]);
        *(__nv_bfloat162*)(Qlo + r * ARS + c + 2) = __floats2bfloat162_rn(ll[2], ll[3]);
    }
    __syncthreads();

    // ---- Q fragments in registers ----
    const int lrow  = (lane & 7) + ((lane >> 3) & 1) * 8;
    const int lkadd = (lane >> 4) * 8;
    const uint32_t qBaseHi = smem_u32(Qhi) + (uint32_t)((wid * 16 + lrow) * ARS + lkadd) * 2;
    const uint32_t qBaseLo = smem_u32(Qlo) + (uint32_t)((wid * 16 + lrow) * ARS + lkadd) * 2;
    uint32_t qh[4][4], ql[4][4];
#pragma unroll
    for (int kc = 0; kc < 4; kc++) {
        ldsm4(qh[kc][0], qh[kc][1], qh[kc][2], qh[kc][3], qBaseHi + kc * 32);
        ldsm4(ql[kc][0], ql[kc][1], ql[kc][2], ql[kc][3], qBaseLo + kc * 32);
    }
    __syncthreads();

    const size_t kvbase = (size_t)(b * HH + h) * SS * DK;
    const __nv_bfloat16* pKhi0 = khi  + kvbase;
    const __nv_bfloat16* pKlo0 = klo  + kvbase;
    const __nv_bfloat16* pVh0  = vthi + kvbase;
    const __nv_bfloat16* pVl0  = vtlo + kvbase;

    const uint32_t sb[2] = { smem_u32(buf0), smem_u32(buf1) };
    const uint32_t fragOff  = (uint32_t)(lrow * ARS + lkadd) * 2;

    float oacc[8][4];
#pragma unroll
    for (int nt = 0; nt < 8; nt++)
#pragma unroll
        for (int r = 0; r < 4; r++) oacc[nt][r] = 0.0f;
    float m0 = -1e30f, m1 = -1e30f, l0 = 0.0f, l1 = 0.0f;

    const int grow0 = qb * 128 + wid * 16 + (lane >> 2);
    const int grow1 = grow0 + 8;
    const int nkt = 2 * qb + 2;

    issue_stage(sb[0], pKhi0, pKlo0, pVh0, pVl0, tid);
    CP_COMMIT();

    for (int kt = 0; kt < nkt; kt++) {
        if (kt + 1 < nkt) {
            int o = (kt + 1) * 64;
            issue_stage(sb[(kt + 1) & 1], pKhi0 + o * DK, pKlo0 + o * DK,
                        pVh0 + o, pVl0 + o, tid);
            CP_COMMIT();
            CP_WAIT(1);
        } else {
            CP_WAIT(0);
        }
        __syncthreads();

        const uint32_t cur = sb[kt & 1];
        const uint32_t kBaseHi = cur + fragOff;
        const uint32_t kBaseLo = cur + (uint32_t)(64 * ARS * 2) + fragOff;
        const uint32_t vBaseHi = cur + (uint32_t)(2 * 64 * ARS * 2) + fragOff;
        const uint32_t vBaseLo = cur + (uint32_t)(3 * 64 * ARS * 2) + fragOff;

        // ---- S = Q K^T ----
        float sacc[8][4];
#pragma unroll
        for (int nt = 0; nt < 8; nt++)
#pragma unroll
            for (int r = 0; r < 4; r++) sacc[nt][r] = 0.0f;

#pragma unroll
        for (int kc = 0; kc < 4; kc++) {
            const uint32_t kb = (uint32_t)(kc * 32);
            uint32_t bH[16], bL[16];
#pragma unroll
            for (int lb = 0; lb < 4; lb++) {
                ldsm4(bH[lb * 4 + 0], bH[lb * 4 + 1], bH[lb * 4 + 2], bH[lb * 4 + 3],
                      kBaseHi + kb + (uint32_t)(lb * 16 * ARS * 2));
                ldsm4(bL[lb * 4 + 0], bL[lb * 4 + 1], bL[lb * 4 + 2], bL[lb * 4 + 3],
                      kBaseLo + kb + (uint32_t)(lb * 16 * ARS * 2));
            }
#pragma unroll
            for (int nt = 0; nt < 8; nt++) {
                const int lo = ((nt >> 1) << 2) + (nt & 1);
                mma16816(sacc[nt], qh[kc], bH[lo], bH[lo + 2]);
                mma16816(sacc[nt], qh[kc], bL[lo], bL[lo + 2]);
                mma16816(sacc[nt], ql[kc], bH[lo], bH[lo + 2]);
            }
        }

        // ---- causal mask ----
        if (kt * 64 + 63 > qb * 128 + wid * 16) {
#pragma unroll
            for (int nt = 0; nt < 8; nt++) {
                int col = kt * 64 + nt * 8 + (lane & 3) * 2;
                if (col > grow0)     sacc[nt][0] = -1e30f;
                if (col + 1 > grow0) sacc[nt][1] = -1e30f;
                if (col > grow1)     sacc[nt][2] = -1e30f;
                if (col + 1 > grow1) sacc[nt][3] = -1e30f;
            }
        }

        // ---- online softmax ----
        float mx0 = -1e30f, mx1 = -1e30f;
#pragma unroll
        for (int nt = 0; nt < 8; nt++) {
            mx0 = fmaxf(mx0, fmaxf(sacc[nt][0], sacc[nt][1]));
            mx1 = fmaxf(mx1, fmaxf(sacc[nt][2], sacc[nt][3]));
        }
        mx0 = fmaxf(mx0, __shfl_xor_sync(0xffffffffu, mx0, 1));
        mx0 = fmaxf(mx0, __shfl_xor_sync(0xffffffffu, mx0, 2));
        mx1 = fmaxf(mx1, __shfl_xor_sync(0xffffffffu, mx1, 1));
        mx1 = fmaxf(mx1, __shfl_xor_sync(0xffffffffu, mx1, 2));
        float mn0 = fmaxf(m0, mx0), mn1 = fmaxf(m1, mx1);
        float cr0 = __expf(m0 - mn0), cr1 = __expf(m1 - mn1);
        float ps0 = 0.0f, ps1 = 0.0f;
#pragma unroll
        for (int nt = 0; nt < 8; nt++) {
            sacc[nt][0] = __expf(sacc[nt][0] - mn0);
            sacc[nt][1] = __expf(sacc[nt][1] - mn0);
            sacc[nt][2] = __expf(sacc[nt][2] - mn1);
            sacc[nt][3] = __expf(sacc[nt][3] - mn1);
            ps0 += sacc[nt][0] + sacc[nt][1];
            ps1 += sacc[nt][2] + sacc[nt][3];
        }
        ps0 += __shfl_xor_sync(0xffffffffu, ps0, 1);
        ps0 += __shfl_xor_sync(0xffffffffu, ps0, 2);
        ps1 += __shfl_xor_sync(0xffffffffu, ps1, 1);
        ps1 += __shfl_xor_sync(0xffffffffu, ps1, 2);
        l0 = l0 * cr0 + ps0;
        l1 = l1 * cr1 + ps1;
        m0 = mn0; m1 = mn1;
#pragma unroll
        for (int nt = 0; nt < 8; nt++) {
            oacc[nt][0] *= cr0; oacc[nt][1] *= cr0;
            oacc[nt][2] *= cr1; oacc[nt][3] *= cr1;
        }

        // ---- O += P V ----
#pragma unroll
        for (int kc = 0; kc < 4; kc++) {
            float f00 = sacc[2*kc][0],   f01 = sacc[2*kc][1];
            float f02 = sacc[2*kc][2],   f03 = sacc[2*kc][3];
            float f10 = sacc[2*kc+1][0], f11 = sacc[2*kc+1][1];
            float f12 = sacc[2*kc+1][2], f13 = sacc[2*kc+1][3];
            __nv_bfloat16 h00 = __float2bfloat16(f00), h01 = __float2bfloat16(f01);
            __nv_bfloat16 h02 = __float2bfloat16(f02), h03 = __float2bfloat16(f03);
            __nv_bfloat16 h10 = __float2bfloat16(f10), h11 = __float2bfloat16(f11);
            __nv_bfloat16 h12 = __float2bfloat16(f12), h13 = __float2bfloat16(f13);
            uint32_t aH[4], aL[4];
            { __nv_bfloat162 t; t.x=h00; t.y=h01; aH[0]=*(uint32_t*)&t; }
            { __nv_bfloat162 t; t.x=h02; t.y=h03; aH[1]=*(uint32_t*)&t; }
            { __nv_bfloat162 t; t.x=h10; t.y=h11; aH[2]=*(uint32_t*)&t; }
            { __nv_bfloat162 t; t.x=h12; t.y=h13; aH[3]=*(uint32_t*)&t; }
            aL[0] = pack_bf2(f00 - __bfloat162float(h00), f01 - __bfloat162float(h01));
            aL[1] = pack_bf2(f02 - __bfloat162float(h02), f03 - __bfloat162float(h03));
            aL[2] = pack_bf2(f10 - __bfloat162float(h10), f11 - __bfloat162float(h11));
            aL[3] = pack_bf2(f12 - __bfloat162float(h12), f13 - __bfloat162float(h13));

            const uint32_t kb = (uint32_t)(kc * 32);
            uint32_t vH[16], vL[16];
#pragma unroll
            for (int lb = 0; lb < 4; lb++) {
                ldsm4(vH[lb * 4 + 0], vH[lb * 4 + 1], vH[lb * 4 + 2], vH[lb * 4 + 3],
                      vBaseHi + kb + (uint32_t)(lb * 16 * ARS * 2));
                ldsm4(vL[lb * 4 + 0], vL[lb * 4 + 1], vL[lb * 4 + 2], vL[lb * 4 + 3],
                      vBaseLo + kb + (uint32_t)(lb * 16 * ARS * 2));
            }
#pragma unroll
            for (int nt = 0; nt < 8; nt++) {
                const int lo = ((nt >> 1) << 2) + (nt & 1);
                mma16816(oacc[nt], aH, vH[lo], vH[lo + 2]);
                mma16816(oacc[nt], aH, vL[lo], vL[lo + 2]);
                mma16816(oacc[nt], aL, vH[lo], vH[lo + 2]);
            }
        }
        __syncthreads();
    }

    // ---- epilogue: write output as bf16 hi/lo ----
    const float inv0 = 1.0f / l0;
    const float inv1 = 1.0f / l1;
    const int row0 = qb * 128 + wid * 16 + (lane >> 2);
#pragma unroll
    for (int nt = 0; nt < 8; nt++) {
        int col = h * DK + nt * 8 + (lane & 3) * 2;
        size_t d0 = ((size_t)(b * SS + row0)) * DD + col;
        size_t d1 = d0 + (size_t)8 * DD;
        float v00 = oacc[nt][0] * inv0, v01 = oacc[nt][1] * inv0;
        float v10 = oacc[nt][2] * inv1, v11 = oacc[nt][3] * inv1;
        __nv_bfloat16 a = __float2bfloat16(v00), c = __float2bfloat16(v01);
        __nv_bfloat16 d = __float2bfloat16(v10), e = __float2bfloat16(v11);
        { __nv_bfloat162 t; t.x = a; t.y = c; *(__nv_bfloat162*)(ohi + d0) = t; }
        { __nv_bfloat162 t; t.x = d; t.y = e; *(__nv_bfloat162*)(ohi + d1) = t; }
        *(__nv_bfloat162*)(olo + d0) =
            __floats2bfloat162_rn(v00 - __bfloat162float(a), v01 - __bfloat162float(c));
        *(__nv_bfloat162*)(olo + d1) =
            __floats2bfloat162_rn(v10 - __bfloat162float(d), v11 - __bfloat162float(e));
    }
}

// ---------------------------------------------------------------------------
extern "C" void kernel_launch(void* const* d_in, const int* in_sizes, int n_in,
                              void* d_out, int out_size) {
    const float* x    = (const float*)d_in[0];
    const int*   pos  = (const int*)d_in[1];
    const float* Wqkv = (const float*)d_in[2];
    const float* Wo   = (const float*)d_in[3];
    float* out = (float*)d_out;

    float *qkv = nullptr;
    __nv_bfloat16 *ahi, *alo, *bhi, *blo, *khi, *klo, *vthi, *vtlo;
    cudaGetSymbolAddress((void**)&qkv, g_qkv);
    cudaGetSymbolAddress((void**)&ahi, g_ahi);
    cudaGetSymbolAddress((void**)&alo, g_alo);
    cudaGetSymbolAddress((void**)&bhi, g_bhi);
    cudaGetSymbolAddress((void**)&blo, g_blo);
    cudaGetSymbolAddress((void**)&khi, g_khi);
    cudaGetSymbolAddress((void**)&klo, g_klo);
    cudaGetSymbolAddress((void**)&vthi, g_vthi);
    cudaGetSymbolAddress((void**)&vtlo, g_vtlo);

    cudaFuncSetAttribute(gemm_mma, cudaFuncAttributeMaxDynamicSharedMemorySize, GEMM_SMEM);
    cudaFuncSetAttribute(attn_mma, cudaFuncAttributeMaxDynamicSharedMemorySize, ATTN_SMEM);

    // 1) split x and Wqkv to bf16 hi/lo
    {
        int n2 = MM * DD / 2;
        split_bf16<<<(n2 + 255) / 256, 256>>>((const float2*)x,
            (__nv_bfloat162*)ahi, (__nv_bfloat162*)alo, n2);
        int w2 = D3 * DD / 2;
        split_bf16<<<(w2 + 255) / 256, 256>>>((const float2*)Wqkv,
            (__nv_bfloat162*)bhi, (__nv_bfloat162*)blo, w2);
    }

    // 2) QKV projection: [8192,1024] x [3072,1024]^T
    {
        dim3 grid(D3 / 128, MM / 128);
        gemm_mma<<<grid, 256, GEMM_SMEM>>>(ahi, alo, bhi, blo, qkv, D3, DD);
    }

    // 3) RoPE (q in place, k split to bf16) + V transpose-split
    {
        int total = BB * SS * HH * (DK / 2);
        rope_split<<<(total + 255) / 256, 256>>>(qkv, pos, khi, klo);
        dim3 gv(SS / 64, BB * HH);
        splitv_t<<<gv, 256>>>(qkv, vthi, vtlo);
    }

    // 4) Causal flash attention (tensor cores, cp.async pipelined)
    {
        dim3 grid(SS / 128, HH, BB);
        attn_mma<<<grid, 256, ATTN_SMEM>>>(qkv, khi, klo, vthi, vtlo, ahi, alo);
    }

    // 5) split Wo, then output projection to fp32 out
    {
        int w2 = DD * DD / 2;
        split_bf16<<<(w2 + 255) / 256, 256>>>((const float2*)Wo,
            (__nv_bfloat162*)bhi, (__nv_bfloat162*)blo, w2);
        dim3 grid(DD / 128, MM / 128);
        gemm_mma<<<grid, 256, GEMM_SMEM>>>(ahi, alo, bhi, blo, out, DD, DD);
    }
}

// round 13
// speedup vs baseline: 1.1250x; 1.0212x over previous
#include <cuda_runtime.h>
#include <cuda_bf16.h>
#include <cstdint>
#include <cstdio>

// Problem constants
#define BB 4
#define SS 2048
#define DD 1024
#define HH 16
#define DK 64
#define D3 3072
#define MM (BB*SS)          // 8192

// Scratch (device globals: allocation-free contract)
__device__ float g_qkv[(size_t)MM * D3];   // [B*S, 3D] : q | k | v
__device__ __nv_bfloat16 g_ahi[(size_t)MM * DD];
__device__ __nv_bfloat16 g_alo[(size_t)MM * DD];
__device__ __nv_bfloat16 g_bhi[(size_t)D3 * DD];
__device__ __nv_bfloat16 g_blo[(size_t)D3 * DD];
__device__ __nv_bfloat16 g_khi[(size_t)MM * DD];   // [b,h,s,dk]
__device__ __nv_bfloat16 g_klo[(size_t)MM * DD];
__device__ __nv_bfloat16 g_vthi[(size_t)MM * DD];  // [b,h,dk,s]
__device__ __nv_bfloat16 g_vtlo[(size_t)MM * DD];

// ---------------------------------------------------------------------------
// helpers
// ---------------------------------------------------------------------------
__device__ __forceinline__ uint32_t smem_u32(const void* p) {
    uint32_t a;
    asm("{ .reg .u64 t; cvta.to.shared.u64 t, %1; cvt.u32.u64 %0, t; }" : "=r"(a) : "l"(p));
    return a;
}
__device__ __forceinline__ void ldsm4(uint32_t& r0, uint32_t& r1, uint32_t& r2,
                                      uint32_t& r3, uint32_t addr) {
    asm volatile("ldmatrix.sync.aligned.m8n8.x4.shared.b16 {%0,%1,%2,%3}, [%4];"
                 : "=r"(r0), "=r"(r1), "=r"(r2), "=r"(r3) : "r"(addr));
}
__device__ __forceinline__ void mma16816(float* c, const uint32_t* a,
                                         uint32_t b0, uint32_t b1) {
    asm volatile(
        "mma.sync.aligned.m16n8k16.row.col.f32.bf16.bf16.f32 "
        "{%0,%1,%2,%3}, {%4,%5,%6,%7}, {%8,%9}, {%0,%1,%2,%3};"
        : "+f"(c[0]), "+f"(c[1]), "+f"(c[2]), "+f"(c[3])
        : "r"(a[0]), "r"(a[1]), "r"(a[2]), "r"(a[3]), "r"(b0), "r"(b1));
}
__device__ __forceinline__ uint32_t pack_bf2(float a, float b) {
    __nv_bfloat162 t = __floats2bfloat162_rn(a, b);
    return *(uint32_t*)&t;
}
__device__ __forceinline__ void cp16(uint32_t dst, const void* src) {
    asm volatile("cp.async.cg.shared.global [%0], [%1], 16;" :: "r"(dst), "l"(src));
}
#define CP_COMMIT() asm volatile("cp.async.commit_group;" ::: "memory")
#define CP_WAIT(n)  asm volatile("cp.async.wait_group %0;" :: "n"(n) : "memory")

// ---------------------------------------------------------------------------
// Split fp32 -> bf16 hi + bf16 lo (2 elements per thread)
// ---------------------------------------------------------------------------
__global__ __launch_bounds__(256) void split_bf16(const float2* __restrict__ x,
                                                  __nv_bfloat162* __restrict__ hi,
                                                  __nv_bfloat162* __restrict__ lo,
                                                  int n2) {
    int i = blockIdx.x * blockDim.x + threadIdx.x;
    if (i >= n2) return;
    float2 v = x[i];
    __nv_bfloat16 hx = __float2bfloat16(v.x);
    __nv_bfloat16 hy = __float2bfloat16(v.y);
    float rx = v.x - __bfloat162float(hx);
    float ry = v.y - __bfloat162float(hy);
    __nv_bfloat162 h; h.x = hx; h.y = hy;
    hi[i] = h;
    lo[i] = __floats2bfloat162_rn(rx, ry);
}

// ---------------------------------------------------------------------------
// Warp-MMA bf16 split-2 GEMM (NT), cp.async double-buffered, KBLK=32.
// CTA tile 128x128. 8 warps: 2(M) x 4(N), warp tile 64x32.
// smem: 2 stages x 4 tiles x [128][40] bf16 = 81920 B -> 2 CTAs/SM.
// Rows stride 80 B: conflict-free LDSM (80r mod 128 distinct), 16B-aligned.
// C += Ahi Bhi^T + Ahi Blo^T + Alo Bhi^T
// ---------------------------------------------------------------------------
#define RS 40
#define TILE_SMB (128 * RS * 2)             // 10240 B per tile
#define GSTAGE_ELE (4 * 128 * RS)           // bf16 per stage
#define GEMM_SMEM (2 * GSTAGE_ELE * 2)      // 81920 B

__device__ __forceinline__ void gemm_issue_stage(
    uint32_t sbase, const __nv_bfloat16* const* srcs, int k0, int K, int tid)
{
#pragma unroll
    for (int t = 0; t < 4; t++) {
        const __nv_bfloat16* src = srcs[t] + k0;
#pragma unroll
        for (int it = 0; it < 2; it++) {
            int q = it * 256 + tid;          // 0..511 16B-chunks (128 rows x 4)
            int r = q >> 2;
            int c = q & 3;
            cp16(sbase + (uint32_t)(t * 128 * RS + r * RS + c * 8) * 2,
                 src + (size_t)r * K + c * 8);
        }
    }
}

__global__ __launch_bounds__(256, 2) void gemm_mma(
    const __nv_bfloat16* __restrict__ Ahi, const __nv_bfloat16* __restrict__ Alo,
    const __nv_bfloat16* __restrict__ Bhi, const __nv_bfloat16* __restrict__ Blo,
    float* __restrict__ C, int N, int K)
{
    extern __shared__ __align__(16) __nv_bfloat16 sm[];

    const int tid  = threadIdx.x;
    const int lane = tid & 31;
    const int wid  = tid >> 5;
    const int wm   = wid & 1;
    const int wn   = wid >> 1;
    const int m0 = blockIdx.y * 128;
    const int n0 = blockIdx.x * 128;

    const __nv_bfloat16* srcs[4] = { Ahi + (size_t)m0 * K, Alo + (size_t)m0 * K,
                                     Bhi + (size_t)n0 * K, Blo + (size_t)n0 * K };

    const int lrow  = (lane & 7) + ((lane >> 3) & 1) * 8;
    const int lkadd = (lane >> 4) * 8;

    const uint32_t sb[2] = { smem_u32(sm), smem_u32(sm + GSTAGE_ELE) };
    const uint32_t aOffHi = (uint32_t)((wm * 64 + lrow) * RS + lkadd) * 2;
    const uint32_t aOffLo = aOffHi + TILE_SMB;
    const uint32_t bOffHi = 2 * TILE_SMB + (uint32_t)((wn * 32 + lrow) * RS + lkadd) * 2;
    const uint32_t bOffLo = bOffHi + TILE_SMB;

    float acc[4][4][4];
#pragma unroll
    for (int i = 0; i < 4; i++)
#pragma unroll
        for (int j = 0; j < 4; j++)
#pragma unroll
            for (int r = 0; r < 4; r++) acc[i][j][r] = 0.0f;

    const int nStages = K >> 5;

    // prologue
    gemm_issue_stage(sb[0], srcs, 0, K, tid);
    CP_COMMIT();

    for (int s = 0; s < nStages; s++) {
        if (s + 1 < nStages) {
            gemm_issue_stage(sb[(s + 1) & 1], srcs, (s + 1) << 5, K, tid);
            CP_COMMIT();
            CP_WAIT(1);
        } else {
            CP_WAIT(0);
        }
        __syncthreads();

        const uint32_t cur = sb[s & 1];
        const uint32_t aBaseHi = cur + aOffHi;
        const uint32_t aBaseLo = cur + aOffLo;
        const uint32_t bBaseHi = cur + bOffHi;
        const uint32_t bBaseLo = cur + bOffLo;

#pragma unroll
        for (int ks = 0; ks < 2; ks++) {
            const uint32_t kb = (uint32_t)(ks * 16 * 2);
            uint32_t bH[8], bL[8];
            ldsm4(bH[0], bH[1], bH[2], bH[3], bBaseHi + kb);
            ldsm4(bH[4], bH[5], bH[6], bH[7], bBaseHi + kb + 16 * RS * 2);
            ldsm4(bL[0], bL[1], bL[2], bL[3], bBaseLo + kb);
            ldsm4(bL[4], bL[5], bL[6], bL[7], bBaseLo + kb + 16 * RS * 2);
#pragma unroll
            for (int mt = 0; mt < 4; mt++) {
                uint32_t aH[4], aL[4];
                const uint32_t moff = (uint32_t)(mt * 16 * RS * 2);
                ldsm4(aH[0], aH[1], aH[2], aH[3], aBaseHi + moff + kb);
                ldsm4(aL[0], aL[1], aL[2], aL[3], aBaseLo + moff + kb);
#pragma unroll
                for (int nt = 0; nt < 4; nt++) {
                    const int lo = ((nt >> 1) << 2) + (nt & 1);
                    mma16816(acc[mt][nt], aH, bH[lo], bH[lo + 2]);
                    mma16816(acc[mt][nt], aH, bL[lo], bL[lo + 2]);
                    mma16816(acc[mt][nt], aL, bH[lo], bH[lo + 2]);
                }
            }
        }
        __syncthreads();
    }

    const int qrow = lane >> 2;
    const int qcol = (lane & 3) * 2;
#pragma unroll
    for (int mt = 0; mt < 4; mt++) {
#pragma unroll
        for (int nt = 0; nt < 4; nt++) {
            float* base = C + (size_t)(m0 + wm * 64 + mt * 16 + qrow) * N
                            + n0 + wn * 32 + nt * 8 + qcol;
            *(float2*)base = make_float2(acc[mt][nt][0], acc[mt][nt][1]);
            *(float2*)(base + (size_t)8 * N) = make_float2(acc[mt][nt][2], acc[mt][nt][3]);
        }
    }
}

// ---------------------------------------------------------------------------
// RoPE: q in-place (fp32); k -> rope'd, split to bf16 hi/lo in [b,h,s,dk].
// ---------------------------------------------------------------------------
__global__ __launch_bounds__(256) void rope_split(float* __restrict__ qkv,
                                                  const int* __restrict__ pos,
                                                  __nv_bfloat16* __restrict__ khi,
                                                  __nv_bfloat16* __restrict__ klo) {
    int p = blockIdx.x * blockDim.x + threadIdx.x;
    if (p >= BB * SS * HH * (DK / 2)) return;
    int j = p & 31;
    int h = (p >> 5) & (HH - 1);
    int s = (p >> 9) & (SS - 1);
    int b = p >> 20;

    float e   = -(float)(2 * j) / (float)DK;
    float inv = powf(10000.0f, e);
    float ang = (float)pos[s] * inv;
    float sn, cs;
    sincosf(ang, &sn, &cs);

    size_t base = ((size_t)(b * SS + s)) * D3 + h * DK + 2 * j;
    float q1 = qkv[base], q2 = qkv[base + 1];
    qkv[base]     = q1 * cs - q2 * sn;
    qkv[base + 1] = q1 * sn + q2 * cs;

    float k1 = qkv[base + DD], k2 = qkv[base + DD + 1];
    float r1 = k1 * cs - k2 * sn;
    float r2 = k1 * sn + k2 * cs;
    __nv_bfloat16 h1 = __float2bfloat16(r1);
    __nv_bfloat16 h2 = __float2bfloat16(r2);
    size_t kdst = (((size_t)(b * HH + h) * SS + s)) * DK + 2 * j;
    __nv_bfloat162 hp; hp.x = h1; hp.y = h2;
    *(__nv_bfloat162*)(khi + kdst) = hp;
    *(__nv_bfloat162*)(klo + kdst) =
        __floats2bfloat162_rn(r1 - __bfloat162float(h1), r2 - __bfloat162float(h2));
}

// ---------------------------------------------------------------------------
// V: transpose + split -> vthi/vtlo [b,h,dk,S]. Tile 64s x 64d via smem.
// ---------------------------------------------------------------------------
__global__ __launch_bounds__(256) void splitv_t(const float* __restrict__ qkv,
                                                __nv_bfloat16* __restrict__ vthi,
                                                __nv_bfloat16* __restrict__ vtlo) {
    __shared__ float t[64][65];
    const int tid = threadIdx.x;
    const int s0 = blockIdx.x * 64;
    const int bh = blockIdx.y;
    const int b = bh >> 4, h = bh & 15;

#pragma unroll
    for (int it = 0; it < 4; it++) {
        int idx = it * 256 + tid;
        int sl = idx >> 4;
        int d4 = (idx & 15) * 4;
        float4 v = *(const float4*)(qkv + ((size_t)(b * SS + s0 + sl)) * D3
                                    + 2 * DD + h * DK + d4);
        t[sl][d4 + 0] = v.x; t[sl][d4 + 1] = v.y;
        t[sl][d4 + 2] = v.z; t[sl][d4 + 3] = v.w;
    }
    __syncthreads();

    const int d  = tid >> 2;
    const int sc = (tid & 3) * 16;
    __nv_bfloat16 hv[16], lv[16];
#pragma unroll
    for (int j = 0; j < 16; j++) {
        float v = t[sc + j][d];
        hv[j] = __float2bfloat16(v);
        lv[j] = __float2bfloat16(v - __bfloat162float(hv[j]));
    }
    size_t dst = ((size_t)(b * HH + h) * DK + d) * SS + s0 + sc;
    *(uint4*)(vthi + dst)     = *(uint4*)&hv[0];
    *(uint4*)(vthi + dst + 8) = *(uint4*)&hv[8];
    *(uint4*)(vtlo + dst)     = *(uint4*)&lv[0];
    *(uint4*)(vtlo + dst + 8) = *(uint4*)&lv[8];
}

// ---------------------------------------------------------------------------
// Tensor-core causal flash attention, cp.async double-buffered (unchanged).
// ---------------------------------------------------------------------------
#define ARS 72
#define STAGE_ELE (4 * 64 * ARS)            // 18432 bf16
#define ATTN_SMEM (2 * STAGE_ELE * 2)       // 73728 B

__device__ __forceinline__ void issue_stage(
    uint32_t sbase, const __nv_bfloat16* pKhi, const __nv_bfloat16* pKlo,
    const __nv_bfloat16* pVh, const __nv_bfloat16* pVl, int tid)
{
#pragma unroll
    for (int i = 0; i < 8; i++) {
        int chunk = i * 256 + tid;      // 2048 x 16B
        int t   = chunk >> 9;
        int c   = chunk & 511;
        int row = c >> 3, col = c & 7;
        uint32_t dst = sbase + (uint32_t)(t * 64 * ARS + row * ARS + col * 8) * 2;
        const __nv_bfloat16* src;
        if (t == 0)      src = pKhi + c * 8;
        else if (t == 1) src = pKlo + c * 8;
        else if (t == 2) src = pVh + (size_t)row * SS + col * 8;
        else             src = pVl + (size_t)row * SS + col * 8;
        cp16(dst, src);
    }
}

__global__ __launch_bounds__(256) void attn_mma(
    const float* __restrict__ qkv,
    const __nv_bfloat16* __restrict__ khi, const __nv_bfloat16* __restrict__ klo,
    const __nv_bfloat16* __restrict__ vthi, const __nv_bfloat16* __restrict__ vtlo,
    __nv_bfloat16* __restrict__ ohi, __nv_bfloat16* __restrict__ olo)
{
    extern __shared__ __align__(16) __nv_bfloat16 as_[];
    __nv_bfloat16* buf0 = as_;
    __nv_bfloat16* buf1 = as_ + STAGE_ELE;

    const int tid  = threadIdx.x;
    const int lane = tid & 31;
    const int wid  = tid >> 5;
    const int qb = blockIdx.x;
    const int h  = blockIdx.y;
    const int b  = blockIdx.z;

    // ---- load Q (scaled 1/8) into buf1 as hi/lo ----
    __nv_bfloat16* Qhi = buf1;
    __nv_bfloat16* Qlo = buf1 + 128 * ARS;
#pragma unroll
    for (int it = 0; it < 8; it++) {
        int idx = it * 256 + tid;
        int r = idx >> 4;
        int c = (idx & 15) * 4;
        const float* src = qkv + ((size_t)(b * SS + qb * 128 + r)) * D3 + h * DK + c;
        float4 v = *(const float4*)src;
        float f[4] = { v.x * 0.125f, v.y * 0.125f, v.z * 0.125f, v.w * 0.125f };
        __nv_bfloat16 hh[4]; float ll[4];
#pragma unroll
        for (int i = 0; i < 4; i++) { hh[i] = __float2bfloat16(f[i]);
                                      ll[i] = f[i] - __bfloat162float(hh[i]); }
        __nv_bfloat162 p0; p0.x = hh[0]; p0.y = hh[1];
        __nv_bfloat162 p1; p1.x = hh[2]; p1.y = hh[3];
        *(__nv_bfloat162*)(Qhi + r * ARS + c)     = p0;
        *(__nv_bfloat162*)(Qhi + r * ARS + c + 2) = p1;
        *(__nv_bfloat162*)(Qlo + r * ARS + c)     = __floats2bfloat162_rn(ll[0], ll[1]);
        *(__nv_bfloat162*)(Qlo + r * ARS + c + 2) = __floats2bfloat162_rn(ll[2], ll[3]);
    }
    __syncthreads();

    // ---- Q fragments in registers ----
    const int lrow  = (lane & 7) + ((lane >> 3) & 1) * 8;
    const int lkadd = (lane >> 4) * 8;
    const uint32_t qBaseHi = smem_u32(Qhi) + (uint32_t)((wid * 16 + lrow) * ARS + lkadd) * 2;
    const uint32_t qBaseLo = smem_u32(Qlo) + (uint32_t)((wid * 16 + lrow) * ARS + lkadd) * 2;
    uint32_t qh[4][4], ql[4][4];
#pragma unroll
    for (int kc = 0; kc < 4; kc++) {
        ldsm4(qh[kc][0], qh[kc][1], qh[kc][2], qh[kc][3], qBaseHi + kc * 32);
        ldsm4(ql[kc][0], ql[kc][1], ql[kc][2], ql[kc][3], qBaseLo + kc * 32);
    }
    __syncthreads();

    const size_t kvbase = (size_t)(b * HH + h) * SS * DK;
    const __nv_bfloat16* pKhi0 = khi  + kvbase;
    const __nv_bfloat16* pKlo0 = klo  + kvbase;
    const __nv_bfloat16* pVh0  = vthi + kvbase;
    const __nv_bfloat16* pVl0  = vtlo + kvbase;

    const uint32_t sb[2] = { smem_u32(buf0), smem_u32(buf1) };
    const uint32_t fragOff  = (uint32_t)(lrow * ARS + lkadd) * 2;

    float oacc[8][4];
#pragma unroll
    for (int nt = 0; nt < 8; nt++)
#pragma unroll
        for (int r = 0; r < 4; r++) oacc[nt][r] = 0.0f;
    float m0 = -1e30f, m1 = -1e30f, l0 = 0.0f, l1 = 0.0f;

    const int grow0 = qb * 128 + wid * 16 + (lane >> 2);
    const int grow1 = grow0 + 8;
    const int nkt = 2 * qb + 2;

    issue_stage(sb[0], pKhi0, pKlo0, pVh0, pVl0, tid);
    CP_COMMIT();

    for (int kt = 0; kt < nkt; kt++) {
        if (kt + 1 < nkt) {
            int o = (kt + 1) * 64;
            issue_stage(sb[(kt + 1) & 1], pKhi0 + o * DK, pKlo0 + o * DK,
                        pVh0 + o, pVl0 + o, tid);
            CP_COMMIT();
            CP_WAIT(1);
        } else {
            CP_WAIT(0);
        }
        __syncthreads();

        const uint32_t cur = sb[kt & 1];
        const uint32_t kBaseHi = cur + fragOff;
        const uint32_t kBaseLo = cur + (uint32_t)(64 * ARS * 2) + fragOff;
        const uint32_t vBaseHi = cur + (uint32_t)(2 * 64 * ARS * 2) + fragOff;
        const uint32_t vBaseLo = cur + (uint32_t)(3 * 64 * ARS * 2) + fragOff;

        // ---- S = Q K^T ----
        float sacc[8][4];
#pragma unroll
        for (int nt = 0; nt < 8; nt++)
#pragma unroll
            for (int r = 0; r < 4; r++) sacc[nt][r] = 0.0f;

#pragma unroll
        for (int kc = 0; kc < 4; kc++) {
            const uint32_t kb = (uint32_t)(kc * 32);
            uint32_t bH[16], bL[16];
#pragma unroll
            for (int lb = 0; lb < 4; lb++) {
                ldsm4(bH[lb * 4 + 0], bH[lb * 4 + 1], bH[lb * 4 + 2], bH[lb * 4 + 3],
                      kBaseHi + kb + (uint32_t)(lb * 16 * ARS * 2));
                ldsm4(bL[lb * 4 + 0], bL[lb * 4 + 1], bL[lb * 4 + 2], bL[lb * 4 + 3],
                      kBaseLo + kb + (uint32_t)(lb * 16 * ARS * 2));
            }
#pragma unroll
            for (int nt = 0; nt < 8; nt++) {
                const int lo = ((nt >> 1) << 2) + (nt & 1);
                mma16816(sacc[nt], qh[kc], bH[lo], bH[lo + 2]);
                mma16816(sacc[nt], qh[kc], bL[lo], bL[lo + 2]);
                mma16816(sacc[nt], ql[kc], bH[lo], bH[lo + 2]);
            }
        }

        // ---- causal mask ----
        if (kt * 64 + 63 > qb * 128 + wid * 16) {
#pragma unroll
            for (int nt = 0; nt < 8; nt++) {
                int col = kt * 64 + nt * 8 + (lane & 3) * 2;
                if (col > grow0)     sacc[nt][0] = -1e30f;
                if (col + 1 > grow0) sacc[nt][1] = -1e30f;
                if (col > grow1)     sacc[nt][2] = -1e30f;
                if (col + 1 > grow1) sacc[nt][3] = -1e30f;
            }
        }

        // ---- online softmax ----
        float mx0 = -1e30f, mx1 = -1e30f;
#pragma unroll
        for (int nt = 0; nt < 8; nt++) {
            mx0 = fmaxf(mx0, fmaxf(sacc[nt][0], sacc[nt][1]));
            mx1 = fmaxf(mx1, fmaxf(sacc[nt][2], sacc[nt][3]));
        }
        mx0 = fmaxf(mx0, __shfl_xor_sync(0xffffffffu, mx0, 1));
        mx0 = fmaxf(mx0, __shfl_xor_sync(0xffffffffu, mx0, 2));
        mx1 = fmaxf(mx1, __shfl_xor_sync(0xffffffffu, mx1, 1));
        mx1 = fmaxf(mx1, __shfl_xor_sync(0xffffffffu, mx1, 2));
        float mn0 = fmaxf(m0, mx0), mn1 = fmaxf(m1, mx1);
        float cr0 = __expf(m0 - mn0), cr1 = __expf(m1 - mn1);
        float ps0 = 0.0f, ps1 = 0.0f;
#pragma unroll
        for (int nt = 0; nt < 8; nt++) {
            sacc[nt][0] = __expf(sacc[nt][0] - mn0);
            sacc[nt][1] = __expf(sacc[nt][1] - mn0);
            sacc[nt][2] = __expf(sacc[nt][2] - mn1);
            sacc[nt][3] = __expf(sacc[nt][3] - mn1);
            ps0 += sacc[nt][0] + sacc[nt][1];
            ps1 += sacc[nt][2] + sacc[nt][3];
        }
        ps0 += __shfl_xor_sync(0xffffffffu, ps0, 1);
        ps0 += __shfl_xor_sync(0xffffffffu, ps0, 2);
        ps1 += __shfl_xor_sync(0xffffffffu, ps1, 1);
        ps1 += __shfl_xor_sync(0xffffffffu, ps1, 2);
        l0 = l0 * cr0 + ps0;
        l1 = l1 * cr1 + ps1;
        m0 = mn0; m1 = mn1;
#pragma unroll
        for (int nt = 0; nt < 8; nt++) {
            oacc[nt][0] *= cr0; oacc[nt][1] *= cr0;
            oacc[nt][2] *= cr1; oacc[nt][3] *= cr1;
        }

        // ---- O += P V ----
#pragma unroll
        for (int kc = 0; kc < 4; kc++) {
            float f00 = sacc[2*kc][0],   f01 = sacc[2*kc][1];
            float f02 = sacc[2*kc][2],   f03 = sacc[2*kc][3];
            float f10 = sacc[2*kc+1][0], f11 = sacc[2*kc+1][1];
            float f12 = sacc[2*kc+1][2], f13 = sacc[2*kc+1][3];
            __nv_bfloat16 h00 = __float2bfloat16(f00), h01 = __float2bfloat16(f01);
            __nv_bfloat16 h02 = __float2bfloat16(f02), h03 = __float2bfloat16(f03);
            __nv_bfloat16 h10 = __float2bfloat16(f10), h11 = __float2bfloat16(f11);
            __nv_bfloat16 h12 = __float2bfloat16(f12), h13 = __float2bfloat16(f13);
            uint32_t aH[4], aL[4];
            { __nv_bfloat162 t; t.x=h00; t.y=h01; aH[0]=*(uint32_t*)&t; }
            { __nv_bfloat162 t; t.x=h02; t.y=h03; aH[1]=*(uint32_t*)&t; }
            { __nv_bfloat162 t; t.x=h10; t.y=h11; aH[2]=*(uint32_t*)&t; }
            { __nv_bfloat162 t; t.x=h12; t.y=h13; aH[3]=*(uint32_t*)&t; }
            aL[0] = pack_bf2(f00 - __bfloat162float(h00), f01 - __bfloat162float(h01));
            aL[1] = pack_bf2(f02 - __bfloat162float(h02), f03 - __bfloat162float(h03));
            aL[2] = pack_bf2(f10 - __bfloat162float(h10), f11 - __bfloat162float(h11));
            aL[3] = pack_bf2(f12 - __bfloat162float(h12), f13 - __bfloat162float(h13));

            const uint32_t kb = (uint32_t)(kc * 32);
            uint32_t vH[16], vL[16];
#pragma unroll
            for (int lb = 0; lb < 4; lb++) {
                ldsm4(vH[lb * 4 + 0], vH[lb * 4 + 1], vH[lb * 4 + 2], vH[lb * 4 + 3],
                      vBaseHi + kb + (uint32_t)(lb * 16 * ARS * 2));
                ldsm4(vL[lb * 4 + 0], vL[lb * 4 + 1], vL[lb * 4 + 2], vL[lb * 4 + 3],
                      vBaseLo + kb + (uint32_t)(lb * 16 * ARS * 2));
            }
#pragma unroll
            for (int nt = 0; nt < 8; nt++) {
                const int lo = ((nt >> 1) << 2) + (nt & 1);
                mma16816(oacc[nt], aH, vH[lo], vH[lo + 2]);
                mma16816(oacc[nt], aH, vL[lo], vL[lo + 2]);
                mma16816(oacc[nt], aL, vH[lo], vH[lo + 2]);
            }
        }
        __syncthreads();
    }

    // ---- epilogue: write output as bf16 hi/lo ----
    const float inv0 = 1.0f / l0;
    const float inv1 = 1.0f / l1;
    const int row0 = qb * 128 + wid * 16 + (lane >> 2);
#pragma unroll
    for (int nt = 0; nt < 8; nt++) {
        int col = h * DK + nt * 8 + (lane & 3) * 2;
        size_t d0 = ((size_t)(b * SS + row0)) * DD + col;
        size_t d1 = d0 + (size_t)8 * DD;
        float v00 = oacc[nt][0] * inv0, v01 = oacc[nt][1] * inv0;
        float v10 = oacc[nt][2] * inv1, v11 = oacc[nt][3] * inv1;
        __nv_bfloat16 a = __float2bfloat16(v00), c = __float2bfloat16(v01);
        __nv_bfloat16 d = __float2bfloat16(v10), e = __float2bfloat16(v11);
        { __nv_bfloat162 t; t.x = a; t.y = c; *(__nv_bfloat162*)(ohi + d0) = t; }
        { __nv_bfloat162 t; t.x = d; t.y = e; *(__nv_bfloat162*)(ohi + d1) = t; }
        *(__nv_bfloat162*)(olo + d0) =
            __floats2bfloat162_rn(v00 - __bfloat162float(a), v01 - __bfloat162float(c));
        *(__nv_bfloat162*)(olo + d1) =
            __floats2bfloat162_rn(v10 - __bfloat162float(d), v11 - __bfloat162float(e));
    }
}

// ---------------------------------------------------------------------------
extern "C" void kernel_launch(void* const* d_in, const int* in_sizes, int n_in,
                              void* d_out, int out_size) {
    const float* x    = (const float*)d_in[0];
    const int*   pos  = (const int*)d_in[1];
    const float* Wqkv = (const float*)d_in[2];
    const float* Wo   = (const float*)d_in[3];
    float* out = (float*)d_out;

    float *qkv = nullptr;
    __nv_bfloat16 *ahi, *alo, *bhi, *blo, *khi, *klo, *vthi, *vtlo;
    cudaGetSymbolAddress((void**)&qkv, g_qkv);
    cudaGetSymbolAddress((void**)&ahi, g_ahi);
    cudaGetSymbolAddress((void**)&alo, g_alo);
    cudaGetSymbolAddress((void**)&bhi, g_bhi);
    cudaGetSymbolAddress((void**)&blo, g_blo);
    cudaGetSymbolAddress((void**)&khi, g_khi);
    cudaGetSymbolAddress((void**)&klo, g_klo);
    cudaGetSymbolAddress((void**)&vthi, g_vthi);
    cudaGetSymbolAddress((void**)&vtlo, g_vtlo);

    cudaFuncSetAttribute(gemm_mma, cudaFuncAttributeMaxDynamicSharedMemorySize, GEMM_SMEM);
    cudaFuncSetAttribute(attn_mma, cudaFuncAttributeMaxDynamicSharedMemorySize, ATTN_SMEM);

    // 1) split x and Wqkv to bf16 hi/lo
    {
        int n2 = MM * DD / 2;
        split_bf16<<<(n2 + 255) / 256, 256>>>((const float2*)x,
            (__nv_bfloat162*)ahi, (__nv_bfloat162*)alo, n2);
        int w2 = D3 * DD / 2;
        split_bf16<<<(w2 + 255) / 256, 256>>>((const float2*)Wqkv,
            (__nv_bfloat162*)bhi, (__nv_bfloat162*)blo, w2);
    }

    // 2) QKV projection: [8192,1024] x [3072,1024]^T
    {
        dim3 grid(D3 / 128, MM / 128);
        gemm_mma<<<grid, 256, GEMM_SMEM>>>(ahi, alo, bhi, blo, qkv, D3, DD);
    }

    // 3) RoPE (q in place, k split to bf16) + V transpose-split
    {
        int total = BB * SS * HH * (DK / 2);
        rope_split<<<(total + 255) / 256, 256>>>(qkv, pos, khi, klo);
        dim3 gv(SS / 64, BB * HH);
        splitv_t<<<gv, 256>>>(qkv, vthi, vtlo);
    }

    // 4) Causal flash attention (tensor cores, cp.async pipelined)
    {
        dim3 grid(SS / 128, HH, BB);
        attn_mma<<<grid, 256, ATTN_SMEM>>>(qkv, khi, klo, vthi, vtlo, ahi, alo);
    }

    // 5) split Wo, then output projection to fp32 out
    {
        int w2 = DD * DD / 2;
        split_bf16<<<(w2 + 255) / 256, 256>>>((const float2*)Wo,
            (__nv_bfloat162*)bhi, (__nv_bfloat162*)blo, w2);
        dim3 grid(DD / 128, MM / 128);
        gemm_mma<<<grid, 256, GEMM_SMEM>>>(ahi, alo, bhi, blo, out, DD, DD);
    }
}

// round 14
// speedup vs baseline: 1.6070x; 1.4285x over previous
#include <cuda_runtime.h>
#include <cuda_fp16.h>
#include <cstdint>
#include <cstdio>

// Problem constants
#define BB 4
#define SS 2048
#define DD 1024
#define HH 16
#define DK 64
#define D3 3072
#define MM (BB*SS)          // 8192

// Scratch (device globals: allocation-free contract)
__device__ float g_qkv[(size_t)MM * D3];   // [B*S, 3D] : q | k | v
__device__ __half g_ah [(size_t)MM * DD];  // activations fp16 (x, then attn out)
__device__ __half g_bhi[(size_t)D3 * DD];  // weights hi
__device__ __half g_blo[(size_t)D3 * DD];  // weights lo
__device__ __half g_khi[(size_t)MM * DD];  // [b,h,s,dk]
__device__ __half g_klo[(size_t)MM * DD];
__device__ __half g_vthi[(size_t)MM * DD]; // [b,h,dk,s]
__device__ __half g_vtlo[(size_t)MM * DD];

// ---------------------------------------------------------------------------
// helpers
// ---------------------------------------------------------------------------
__device__ __forceinline__ uint32_t smem_u32(const void* p) {
    uint32_t a;
    asm("{ .reg .u64 t; cvta.to.shared.u64 t, %1; cvt.u32.u64 %0, t; }" : "=r"(a) : "l"(p));
    return a;
}
__device__ __forceinline__ void ldsm4(uint32_t& r0, uint32_t& r1, uint32_t& r2,
                                      uint32_t& r3, uint32_t addr) {
    asm volatile("ldmatrix.sync.aligned.m8n8.x4.shared.b16 {%0,%1,%2,%3}, [%4];"
                 : "=r"(r0), "=r"(r1), "=r"(r2), "=r"(r3) : "r"(addr));
}
__device__ __forceinline__ void mma16816(float* c, const uint32_t* a,
                                         uint32_t b0, uint32_t b1) {
    asm volatile(
        "mma.sync.aligned.m16n8k16.row.col.f32.f16.f16.f32 "
        "{%0,%1,%2,%3}, {%4,%5,%6,%7}, {%8,%9}, {%0,%1,%2,%3};"
        : "+f"(c[0]), "+f"(c[1]), "+f"(c[2]), "+f"(c[3])
        : "r"(a[0]), "r"(a[1]), "r"(a[2]), "r"(a[3]), "r"(b0), "r"(b1));
}
__device__ __forceinline__ uint32_t pack_h2(float a, float b) {
    __half2 t = __floats2half2_rn(a, b);   // .x = a in low bits
    return *(uint32_t*)&t;
}
__device__ __forceinline__ void cp16(uint32_t dst, const void* src) {
    asm volatile("cp.async.cg.shared.global [%0], [%1], 16;" :: "r"(dst), "l"(src));
}
#define CP_COMMIT() asm volatile("cp.async.commit_group;" ::: "memory")
#define CP_WAIT(n)  asm volatile("cp.async.wait_group %0;" :: "n"(n) : "memory")

// ---------------------------------------------------------------------------
// cast fp32 -> fp16 (activations, hi only)
// ---------------------------------------------------------------------------
__global__ __launch_bounds__(256) void cast_fp16(const float2* __restrict__ x,
                                                 __half2* __restrict__ hi, int n2) {
    int i = blockIdx.x * blockDim.x + threadIdx.x;
    if (i >= n2) return;
    float2 v = x[i];
    hi[i] = __floats2half2_rn(v.x, v.y);
}

// Split fp32 -> fp16 hi + fp16 lo (weights)
__global__ __launch_bounds__(256) void split_fp16(const float2* __restrict__ x,
                                                  __half2* __restrict__ hi,
                                                  __half2* __restrict__ lo, int n2) {
    int i = blockIdx.x * blockDim.x + threadIdx.x;
    if (i >= n2) return;
    float2 v = x[i];
    __half hx = __float2half_rn(v.x);
    __half hy = __float2half_rn(v.y);
    hi[i] = __halves2half2(hx, hy);
    lo[i] = __floats2half2_rn(v.x - __half2float(hx), v.y - __half2float(hy));
}

// ---------------------------------------------------------------------------
// Warp-MMA fp16 GEMM (NT), cp.async double-buffered, KBLK=32, 2-pass split:
//   C = Ah * Bhi^T + Ah * Blo^T        (A = activations, fp16 hi only)
// CTA tile 128x128. 8 warps: 2(M) x 4(N), warp tile 64x32.
// smem: 2 stages x 3 tiles x [128][40] fp16 = 61440 B -> 2 CTAs/SM.
// ---------------------------------------------------------------------------
#define RS 40
#define TILE_SMB (128 * RS * 2)             // 10240 B per tile
#define GSTAGE_ELE (3 * 128 * RS)           // fp16 per stage
#define GEMM_SMEM (2 * GSTAGE_ELE * 2)      // 61440 B

__device__ __forceinline__ void gemm_issue_stage(
    uint32_t sbase, const __half* const* srcs, int k0, int K, int tid)
{
#pragma unroll
    for (int t = 0; t < 3; t++) {
        const __half* src = srcs[t] + k0;
#pragma unroll
        for (int it = 0; it < 2; it++) {
            int q = it * 256 + tid;          // 0..511 16B-chunks (128 rows x 4)
            int r = q >> 2;
            int c = q & 3;
            cp16(sbase + (uint32_t)(t * 128 * RS + r * RS + c * 8) * 2,
                 src + (size_t)r * K + c * 8);
        }
    }
}

__global__ __launch_bounds__(256, 2) void gemm_mma(
    const __half* __restrict__ Ah,
    const __half* __restrict__ Bhi, const __half* __restrict__ Blo,
    float* __restrict__ C, int N, int K)
{
    extern __shared__ __align__(16) __half sm[];

    const int tid  = threadIdx.x;
    const int lane = tid & 31;
    const int wid  = tid >> 5;
    const int wm   = wid & 1;
    const int wn   = wid >> 1;
    const int m0 = blockIdx.y * 128;
    const int n0 = blockIdx.x * 128;

    const __half* srcs[3] = { Ah + (size_t)m0 * K,
                              Bhi + (size_t)n0 * K, Blo + (size_t)n0 * K };

    const int lrow  = (lane & 7) + ((lane >> 3) & 1) * 8;
    const int lkadd = (lane >> 4) * 8;

    const uint32_t sb[2] = { smem_u32(sm), smem_u32(sm + GSTAGE_ELE) };
    const uint32_t aOff   = (uint32_t)((wm * 64 + lrow) * RS + lkadd) * 2;
    const uint32_t bOffHi = TILE_SMB + (uint32_t)((wn * 32 + lrow) * RS + lkadd) * 2;
    const uint32_t bOffLo = bOffHi + TILE_SMB;

    float acc[4][4][4];
#pragma unroll
    for (int i = 0; i < 4; i++)
#pragma unroll
        for (int j = 0; j < 4; j++)
#pragma unroll
            for (int r = 0; r < 4; r++) acc[i][j][r] = 0.0f;

    const int nStages = K >> 5;

    gemm_issue_stage(sb[0], srcs, 0, K, tid);
    CP_COMMIT();

    for (int s = 0; s < nStages; s++) {
        if (s + 1 < nStages) {
            gemm_issue_stage(sb[(s + 1) & 1], srcs, (s + 1) << 5, K, tid);
            CP_COMMIT();
            CP_WAIT(1);
        } else {
            CP_WAIT(0);
        }
        __syncthreads();

        const uint32_t cur = sb[s & 1];
        const uint32_t aBase   = cur + aOff;
        const uint32_t bBaseHi = cur + bOffHi;
        const uint32_t bBaseLo = cur + bOffLo;

#pragma unroll
        for (int ks = 0; ks < 2; ks++) {
            const uint32_t kb = (uint32_t)(ks * 16 * 2);
            uint32_t bH[8], bL[8];
            ldsm4(bH[0], bH[1], bH[2], bH[3], bBaseHi + kb);
            ldsm4(bH[4], bH[5], bH[6], bH[7], bBaseHi + kb + 16 * RS * 2);
            ldsm4(bL[0], bL[1], bL[2], bL[3], bBaseLo + kb);
            ldsm4(bL[4], bL[5], bL[6], bL[7], bBaseLo + kb + 16 * RS * 2);
#pragma unroll
            for (int mt = 0; mt < 4; mt++) {
                uint32_t aH[4];
                const uint32_t moff = (uint32_t)(mt * 16 * RS * 2);
                ldsm4(aH[0], aH[1], aH[2], aH[3], aBase + moff + kb);
#pragma unroll
                for (int nt = 0; nt < 4; nt++) {
                    const int lo = ((nt >> 1) << 2) + (nt & 1);
                    mma16816(acc[mt][nt], aH, bH[lo], bH[lo + 2]);
                    mma16816(acc[mt][nt], aH, bL[lo], bL[lo + 2]);
                }
            }
        }
        __syncthreads();
    }

    const int qrow = lane >> 2;
    const int qcol = (lane & 3) * 2;
#pragma unroll
    for (int mt = 0; mt < 4; mt++) {
#pragma unroll
        for (int nt = 0; nt < 4; nt++) {
            float* base = C + (size_t)(m0 + wm * 64 + mt * 16 + qrow) * N
                            + n0 + wn * 32 + nt * 8 + qcol;
            *(float2*)base = make_float2(acc[mt][nt][0], acc[mt][nt][1]);
            *(float2*)(base + (size_t)8 * N) = make_float2(acc[mt][nt][2], acc[mt][nt][3]);
        }
    }
}

// ---------------------------------------------------------------------------
// RoPE: q in-place (fp32); k -> rope'd, split to fp16 hi/lo in [b,h,s,dk].
// ---------------------------------------------------------------------------
__global__ __launch_bounds__(256) void rope_split(float* __restrict__ qkv,
                                                  const int* __restrict__ pos,
                                                  __half* __restrict__ khi,
                                                  __half* __restrict__ klo) {
    int p = blockIdx.x * blockDim.x + threadIdx.x;
    if (p >= BB * SS * HH * (DK / 2)) return;
    int j = p & 31;
    int h = (p >> 5) & (HH - 1);
    int s = (p >> 9) & (SS - 1);
    int b = p >> 20;

    float e   = -(float)(2 * j) / (float)DK;
    float inv = powf(10000.0f, e);
    float ang = (float)pos[s] * inv;
    float sn, cs;
    sincosf(ang, &sn, &cs);

    size_t base = ((size_t)(b * SS + s)) * D3 + h * DK + 2 * j;
    float q1 = qkv[base], q2 = qkv[base + 1];
    qkv[base]     = q1 * cs - q2 * sn;
    qkv[base + 1] = q1 * sn + q2 * cs;

    float k1 = qkv[base + DD], k2 = qkv[base + DD + 1];
    float r1 = k1 * cs - k2 * sn;
    float r2 = k1 * sn + k2 * cs;
    __half h1 = __float2half_rn(r1);
    __half h2 = __float2half_rn(r2);
    size_t kdst = (((size_t)(b * HH + h) * SS + s)) * DK + 2 * j;
    *(__half2*)(khi + kdst) = __halves2half2(h1, h2);
    *(__half2*)(klo + kdst) =
        __floats2half2_rn(r1 - __half2float(h1), r2 - __half2float(h2));
}

// ---------------------------------------------------------------------------
// V: transpose + split -> vthi/vtlo [b,h,dk,S]. Tile 64s x 64d via smem.
// ---------------------------------------------------------------------------
__global__ __launch_bounds__(256) void splitv_t(const float* __restrict__ qkv,
                                                __half* __restrict__ vthi,
                                                __half* __restrict__ vtlo) {
    __shared__ float t[64][65];
    const int tid = threadIdx.x;
    const int s0 = blockIdx.x * 64;
    const int bh = blockIdx.y;
    const int b = bh >> 4, h = bh & 15;

#pragma unroll
    for (int it = 0; it < 4; it++) {
        int idx = it * 256 + tid;
        int sl = idx >> 4;
        int d4 = (idx & 15) * 4;
        float4 v = *(const float4*)(qkv + ((size_t)(b * SS + s0 + sl)) * D3
                                    + 2 * DD + h * DK + d4);
        t[sl][d4 + 0] = v.x; t[sl][d4 + 1] = v.y;
        t[sl][d4 + 2] = v.z; t[sl][d4 + 3] = v.w;
    }
    __syncthreads();

    const int d  = tid >> 2;
    const int sc = (tid & 3) * 16;
    __half hv[16], lv[16];
#pragma unroll
    for (int j = 0; j < 16; j++) {
        float v = t[sc + j][d];
        hv[j] = __float2half_rn(v);
        lv[j] = __float2half_rn(v - __half2float(hv[j]));
    }
    size_t dst = ((size_t)(b * HH + h) * DK + d) * SS + s0 + sc;
    *(uint4*)(vthi + dst)     = *(uint4*)&hv[0];
    *(uint4*)(vthi + dst + 8) = *(uint4*)&hv[8];
    *(uint4*)(vtlo + dst)     = *(uint4*)&lv[0];
    *(uint4*)(vtlo + dst + 8) = *(uint4*)&lv[8];
}

// ---------------------------------------------------------------------------
// Tensor-core causal flash attention, fp16 2-pass split.
// Q/P: fp16 hi only (A side). K/V: fp16 hi+lo (B side).
// Stage = {Khi, Klo, Vthi, Vtlo} each [64][72]; 2 stages, cp.async.
// Output: fp16 hi only (feeds out-proj A operand).
// ---------------------------------------------------------------------------
#define ARS 72
#define STAGE_ELE (4 * 64 * ARS)            // 18432 fp16
#define ATTN_SMEM (2 * STAGE_ELE * 2)       // 73728 B

__device__ __forceinline__ void issue_stage(
    uint32_t sbase, const __half* pKhi, const __half* pKlo,
    const __half* pVh, const __half* pVl, int tid)
{
#pragma unroll
    for (int i = 0; i < 8; i++) {
        int chunk = i * 256 + tid;      // 2048 x 16B
        int t   = chunk >> 9;
        int c   = chunk & 511;
        int row = c >> 3, col = c & 7;
        uint32_t dst = sbase + (uint32_t)(t * 64 * ARS + row * ARS + col * 8) * 2;
        const __half* src;
        if (t == 0)      src = pKhi + c * 8;
        else if (t == 1) src = pKlo + c * 8;
        else if (t == 2) src = pVh + (size_t)row * SS + col * 8;
        else             src = pVl + (size_t)row * SS + col * 8;
        cp16(dst, src);
    }
}

__global__ __launch_bounds__(256) void attn_mma(
    const float* __restrict__ qkv,
    const __half* __restrict__ khi, const __half* __restrict__ klo,
    const __half* __restrict__ vthi, const __half* __restrict__ vtlo,
    __half* __restrict__ ohi)
{
    extern __shared__ __align__(16) __half as_[];
    __half* buf0 = as_;
    __half* buf1 = as_ + STAGE_ELE;

    const int tid  = threadIdx.x;
    const int lane = tid & 31;
    const int wid  = tid >> 5;
    const int qb = blockIdx.x;
    const int h  = blockIdx.y;
    const int b  = blockIdx.z;

    // ---- load Q (scaled 1/8) into buf1 as fp16 hi ----
    __half* Qh = buf1;
#pragma unroll
    for (int it = 0; it < 8; it++) {
        int idx = it * 256 + tid;
        int r = idx >> 4;
        int c = (idx & 15) * 4;
        const float* src = qkv + ((size_t)(b * SS + qb * 128 + r)) * D3 + h * DK + c;
        float4 v = *(const float4*)src;
        *(__half2*)(Qh + r * ARS + c)     = __floats2half2_rn(v.x * 0.125f, v.y * 0.125f);
        *(__half2*)(Qh + r * ARS + c + 2) = __floats2half2_rn(v.z * 0.125f, v.w * 0.125f);
    }
    __syncthreads();

    // ---- Q fragments in registers ----
    const int lrow  = (lane & 7) + ((lane >> 3) & 1) * 8;
    const int lkadd = (lane >> 4) * 8;
    const uint32_t qBase = smem_u32(Qh) + (uint32_t)((wid * 16 + lrow) * ARS + lkadd) * 2;
    uint32_t qh[4][4];
#pragma unroll
    for (int kc = 0; kc < 4; kc++)
        ldsm4(qh[kc][0], qh[kc][1], qh[kc][2], qh[kc][3], qBase + kc * 32);
    __syncthreads();

    const size_t kvbase = (size_t)(b * HH + h) * SS * DK;
    const __half* pKhi0 = khi  + kvbase;
    const __half* pKlo0 = klo  + kvbase;
    const __half* pVh0  = vthi + kvbase;
    const __half* pVl0  = vtlo + kvbase;

    const uint32_t sb[2] = { smem_u32(buf0), smem_u32(buf1) };
    const uint32_t fragOff  = (uint32_t)(lrow * ARS + lkadd) * 2;

    float oacc[8][4];
#pragma unroll
    for (int nt = 0; nt < 8; nt++)
#pragma unroll
        for (int r = 0; r < 4; r++) oacc[nt][r] = 0.0f;
    float m0 = -1e30f, m1 = -1e30f, l0 = 0.0f, l1 = 0.0f;

    const int grow0 = qb * 128 + wid * 16 + (lane >> 2);
    const int grow1 = grow0 + 8;
    const int nkt = 2 * qb + 2;

    issue_stage(sb[0], pKhi0, pKlo0, pVh0, pVl0, tid);
    CP_COMMIT();

    for (int kt = 0; kt < nkt; kt++) {
        if (kt + 1 < nkt) {
            int o = (kt + 1) * 64;
            issue_stage(sb[(kt + 1) & 1], pKhi0 + o * DK, pKlo0 + o * DK,
                        pVh0 + o, pVl0 + o, tid);
            CP_COMMIT();
            CP_WAIT(1);
        } else {
            CP_WAIT(0);
        }
        __syncthreads();

        const uint32_t cur = sb[kt & 1];
        const uint32_t kBaseHi = cur + fragOff;
        const uint32_t kBaseLo = cur + (uint32_t)(64 * ARS * 2) + fragOff;
        const uint32_t vBaseHi = cur + (uint32_t)(2 * 64 * ARS * 2) + fragOff;
        const uint32_t vBaseLo = cur + (uint32_t)(3 * 64 * ARS * 2) + fragOff;

        // ---- S = Q K^T (2-pass) ----
        float sacc[8][4];
#pragma unroll
        for (int nt = 0; nt < 8; nt++)
#pragma unroll
            for (int r = 0; r < 4; r++) sacc[nt][r] = 0.0f;

#pragma unroll
        for (int kc = 0; kc < 4; kc++) {
            const uint32_t kb = (uint32_t)(kc * 32);
            uint32_t bH[16], bL[16];
#pragma unroll
            for (int lb = 0; lb < 4; lb++) {
                ldsm4(bH[lb * 4 + 0], bH[lb * 4 + 1], bH[lb * 4 + 2], bH[lb * 4 + 3],
                      kBaseHi + kb + (uint32_t)(lb * 16 * ARS * 2));
                ldsm4(bL[lb * 4 + 0], bL[lb * 4 + 1], bL[lb * 4 + 2], bL[lb * 4 + 3],
                      kBaseLo + kb + (uint32_t)(lb * 16 * ARS * 2));
            }
#pragma unroll
            for (int nt = 0; nt < 8; nt++) {
                const int lo = ((nt >> 1) << 2) + (nt & 1);
                mma16816(sacc[nt], qh[kc], bH[lo], bH[lo + 2]);
                mma16816(sacc[nt], qh[kc], bL[lo], bL[lo + 2]);
            }
        }

        // ---- causal mask ----
        if (kt * 64 + 63 > qb * 128 + wid * 16) {
#pragma unroll
            for (int nt = 0; nt < 8; nt++) {
                int col = kt * 64 + nt * 8 + (lane & 3) * 2;
                if (col > grow0)     sacc[nt][0] = -1e30f;
                if (col + 1 > grow0) sacc[nt][1] = -1e30f;
                if (col > grow1)     sacc[nt][2] = -1e30f;
                if (col + 1 > grow1) sacc[nt][3] = -1e30f;
            }
        }

        // ---- online softmax ----
        float mx0 = -1e30f, mx1 = -1e30f;
#pragma unroll
        for (int nt = 0; nt < 8; nt++) {
            mx0 = fmaxf(mx0, fmaxf(sacc[nt][0], sacc[nt][1]));
            mx1 = fmaxf(mx1, fmaxf(sacc[nt][2], sacc[nt][3]));
        }
        mx0 = fmaxf(mx0, __shfl_xor_sync(0xffffffffu, mx0, 1));
        mx0 = fmaxf(mx0, __shfl_xor_sync(0xffffffffu, mx0, 2));
        mx1 = fmaxf(mx1, __shfl_xor_sync(0xffffffffu, mx1, 1));
        mx1 = fmaxf(mx1, __shfl_xor_sync(0xffffffffu, mx1, 2));
        float mn0 = fmaxf(m0, mx0), mn1 = fmaxf(m1, mx1);
        float cr0 = __expf(m0 - mn0), cr1 = __expf(m1 - mn1);
        float ps0 = 0.0f, ps1 = 0.0f;
#pragma unroll
        for (int nt = 0; nt < 8; nt++) {
            sacc[nt][0] = __expf(sacc[nt][0] - mn0);
            sacc[nt][1] = __expf(sacc[nt][1] - mn0);
            sacc[nt][2] = __expf(sacc[nt][2] - mn1);
            sacc[nt][3] = __expf(sacc[nt][3] - mn1);
            ps0 += sacc[nt][0] + sacc[nt][1];
            ps1 += sacc[nt][2] + sacc[nt][3];
        }
        ps0 += __shfl_xor_sync(0xffffffffu, ps0, 1);
        ps0 += __shfl_xor_sync(0xffffffffu, ps0, 2);
        ps1 += __shfl_xor_sync(0xffffffffu, ps1, 1);
        ps1 += __shfl_xor_sync(0xffffffffu, ps1, 2);
        l0 = l0 * cr0 + ps0;
        l1 = l1 * cr1 + ps1;
        m0 = mn0; m1 = mn1;
#pragma unroll
        for (int nt = 0; nt < 8; nt++) {
            oacc[nt][0] *= cr0; oacc[nt][1] *= cr0;
            oacc[nt][2] *= cr1; oacc[nt][3] *= cr1;
        }

        // ---- O += P V (2-pass, P fp16 hi only) ----
#pragma unroll
        for (int kc = 0; kc < 4; kc++) {
            uint32_t aH[4];
            aH[0] = pack_h2(sacc[2*kc][0],   sacc[2*kc][1]);
            aH[1] = pack_h2(sacc[2*kc][2],   sacc[2*kc][3]);
            aH[2] = pack_h2(sacc[2*kc+1][0], sacc[2*kc+1][1]);
            aH[3] = pack_h2(sacc[2*kc+1][2], sacc[2*kc+1][3]);

            const uint32_t kb = (uint32_t)(kc * 32);
            uint32_t vH[16], vL[16];
#pragma unroll
            for (int lb = 0; lb < 4; lb++) {
                ldsm4(vH[lb * 4 + 0], vH[lb * 4 + 1], vH[lb * 4 + 2], vH[lb * 4 + 3],
                      vBaseHi + kb + (uint32_t)(lb * 16 * ARS * 2));
                ldsm4(vL[lb * 4 + 0], vL[lb * 4 + 1], vL[lb * 4 + 2], vL[lb * 4 + 3],
                      vBaseLo + kb + (uint32_t)(lb * 16 * ARS * 2));
            }
#pragma unroll
            for (int nt = 0; nt < 8; nt++) {
                const int lo = ((nt >> 1) << 2) + (nt & 1);
                mma16816(oacc[nt], aH, vH[lo], vH[lo + 2]);
                mma16816(oacc[nt], aH, vL[lo], vL[lo + 2]);
            }
        }
        __syncthreads();
    }

    // ---- epilogue: write output as fp16 hi ----
    const float inv0 = 1.0f / l0;
    const float inv1 = 1.0f / l1;
    const int row0 = qb * 128 + wid * 16 + (lane >> 2);
#pragma unroll
    for (int nt = 0; nt < 8; nt++) {
        int col = h * DK + nt * 8 + (lane & 3) * 2;
        size_t d0 = ((size_t)(b * SS + row0)) * DD + col;
        size_t d1 = d0 + (size_t)8 * DD;
        *(__half2*)(ohi + d0) = __floats2half2_rn(oacc[nt][0] * inv0, oacc[nt][1] * inv0);
        *(__half2*)(ohi + d1) = __floats2half2_rn(oacc[nt][2] * inv1, oacc[nt][3] * inv1);
    }
}

// ---------------------------------------------------------------------------
extern "C" void kernel_launch(void* const* d_in, const int* in_sizes, int n_in,
                              void* d_out, int out_size) {
    const float* x    = (const float*)d_in[0];
    const int*   pos  = (const int*)d_in[1];
    const float* Wqkv = (const float*)d_in[2];
    const float* Wo   = (const float*)d_in[3];
    float* out = (float*)d_out;

    float *qkv = nullptr;
    __half *ah, *bhi, *blo, *khi, *klo, *vthi, *vtlo;
    cudaGetSymbolAddress((void**)&qkv, g_qkv);
    cudaGetSymbolAddress((void**)&ah,  g_ah);
    cudaGetSymbolAddress((void**)&bhi, g_bhi);
    cudaGetSymbolAddress((void**)&blo, g_blo);
    cudaGetSymbolAddress((void**)&khi, g_khi);
    cudaGetSymbolAddress((void**)&klo, g_klo);
    cudaGetSymbolAddress((void**)&vthi, g_vthi);
    cudaGetSymbolAddress((void**)&vtlo, g_vtlo);

    cudaFuncSetAttribute(gemm_mma, cudaFuncAttributeMaxDynamicSharedMemorySize, GEMM_SMEM);
    cudaFuncSetAttribute(attn_mma, cudaFuncAttributeMaxDynamicSharedMemorySize, ATTN_SMEM);

    // 1) cast x to fp16; split Wqkv to fp16 hi/lo
    {
        int n2 = MM * DD / 2;
        cast_fp16<<<(n2 + 255) / 256, 256>>>((const float2*)x, (__half2*)ah, n2);
        int w2 = D3 * DD / 2;
        split_fp16<<<(w2 + 255) / 256, 256>>>((const float2*)Wqkv,
            (__half2*)bhi, (__half2*)blo, w2);
    }

    // 2) QKV projection: [8192,1024] x [3072,1024]^T
    {
        dim3 grid(D3 / 128, MM / 128);
        gemm_mma<<<grid, 256, GEMM_SMEM>>>(ah, bhi, blo, qkv, D3, DD);
    }

    // 3) RoPE (q in place, k split to fp16) + V transpose-split
    {
        int total = BB * SS * HH * (DK / 2);
        rope_split<<<(total + 255) / 256, 256>>>(qkv, pos, khi, klo);
        dim3 gv(SS / 64, BB * HH);
        splitv_t<<<gv, 256>>>(qkv, vthi, vtlo);
    }

    // 4) Causal flash attention -> fp16 output into ah
    {
        dim3 grid(SS / 128, HH, BB);
        attn_mma<<<grid, 256, ATTN_SMEM>>>(qkv, khi, klo, vthi, vtlo, ah);
    }

    // 5) split Wo, then output projection to fp32 out
    {
        int w2 = DD * DD / 2;
        split_fp16<<<(w2 + 255) / 256, 256>>>((const float2*)Wo,
            (__half2*)bhi, (__half2*)blo, w2);
        dim3 grid(DD / 128, MM / 128);
        gemm_mma<<<grid, 256, GEMM_SMEM>>>(ah, bhi, blo, out, DD, DD);
    }
}

// round 15
// speedup vs baseline: 1.8795x; 1.1696x over previous
#include <cuda_runtime.h>
#include <cuda_fp16.h>
#include <cstdint>
#include <cstdio>

// Problem constants
#define BB 4
#define SS 2048
#define DD 1024
#define HH 16
#define DK 64
#define D3 3072
#define MM (BB*SS)          // 8192

// Scratch (device globals: allocation-free contract)
__device__ float g_qkv[(size_t)MM * D3];   // [B*S, 3D] : q | k | v
__device__ __half g_ah [(size_t)MM * DD];  // activations fp16 (x, then attn out)
__device__ __half g_bhi[(size_t)D3 * DD];  // weights hi
__device__ __half g_blo[(size_t)D3 * DD];  // weights lo
__device__ __half g_khi[(size_t)MM * DD];  // [b,h,s,dk]  (rope'd K, fp16)
__device__ __half g_vthi[(size_t)MM * DD]; // [b,h,dk,s]  (V transposed, fp16)

// ---------------------------------------------------------------------------
// helpers
// ---------------------------------------------------------------------------
__device__ __forceinline__ uint32_t smem_u32(const void* p) {
    uint32_t a;
    asm("{ .reg .u64 t; cvta.to.shared.u64 t, %1; cvt.u32.u64 %0, t; }" : "=r"(a) : "l"(p));
    return a;
}
__device__ __forceinline__ void ldsm4(uint32_t& r0, uint32_t& r1, uint32_t& r2,
                                      uint32_t& r3, uint32_t addr) {
    asm volatile("ldmatrix.sync.aligned.m8n8.x4.shared.b16 {%0,%1,%2,%3}, [%4];"
                 : "=r"(r0), "=r"(r1), "=r"(r2), "=r"(r3) : "r"(addr));
}
__device__ __forceinline__ void mma16816(float* c, const uint32_t* a,
                                         uint32_t b0, uint32_t b1) {
    asm volatile(
        "mma.sync.aligned.m16n8k16.row.col.f32.f16.f16.f32 "
        "{%0,%1,%2,%3}, {%4,%5,%6,%7}, {%8,%9}, {%0,%1,%2,%3};"
        : "+f"(c[0]), "+f"(c[1]), "+f"(c[2]), "+f"(c[3])
        : "r"(a[0]), "r"(a[1]), "r"(a[2]), "r"(a[3]), "r"(b0), "r"(b1));
}
__device__ __forceinline__ uint32_t pack_h2(float a, float b) {
    __half2 t = __floats2half2_rn(a, b);
    return *(uint32_t*)&t;
}
__device__ __forceinline__ void cp16(uint32_t dst, const void* src) {
    asm volatile("cp.async.cg.shared.global [%0], [%1], 16;" :: "r"(dst), "l"(src));
}
#define CP_COMMIT() asm volatile("cp.async.commit_group;" ::: "memory")
#define CP_WAIT(n)  asm volatile("cp.async.wait_group %0;" :: "n"(n) : "memory")

// ---------------------------------------------------------------------------
// cast fp32 -> fp16 (activations, hi only)
// ---------------------------------------------------------------------------
__global__ __launch_bounds__(256) void cast_fp16(const float2* __restrict__ x,
                                                 __half2* __restrict__ hi, int n2) {
    int i = blockIdx.x * blockDim.x + threadIdx.x;
    if (i >= n2) return;
    float2 v = x[i];
    hi[i] = __floats2half2_rn(v.x, v.y);
}

// Split fp32 -> fp16 hi + fp16 lo (weights)
__global__ __launch_bounds__(256) void split_fp16(const float2* __restrict__ x,
                                                  __half2* __restrict__ hi,
                                                  __half2* __restrict__ lo, int n2) {
    int i = blockIdx.x * blockDim.x + threadIdx.x;
    if (i >= n2) return;
    float2 v = x[i];
    __half hx = __float2half_rn(v.x);
    __half hy = __float2half_rn(v.y);
    hi[i] = __halves2half2(hx, hy);
    lo[i] = __floats2half2_rn(v.x - __half2float(hx), v.y - __half2float(hy));
}

// ---------------------------------------------------------------------------
// Warp-MMA fp16 GEMM (NT), cp.async double-buffered, KBLK=32, 2-pass split:
//   C = Ah * Bhi^T + Ah * Blo^T        (A = activations, fp16 hi only)
// CTA tile 128x128. 8 warps: 2(M) x 4(N), warp tile 64x32.
// smem: 2 stages x 3 tiles x [128][40] fp16 = 61440 B -> 2 CTAs/SM.
// ---------------------------------------------------------------------------
#define RS 40
#define TILE_SMB (128 * RS * 2)             // 10240 B per tile
#define GSTAGE_ELE (3 * 128 * RS)           // fp16 per stage
#define GEMM_SMEM (2 * GSTAGE_ELE * 2)      // 61440 B

__device__ __forceinline__ void gemm_issue_stage(
    uint32_t sbase, const __half* const* srcs, int k0, int K, int tid)
{
#pragma unroll
    for (int t = 0; t < 3; t++) {
        const __half* src = srcs[t] + k0;
#pragma unroll
        for (int it = 0; it < 2; it++) {
            int q = it * 256 + tid;          // 0..511 16B-chunks (128 rows x 4)
            int r = q >> 2;
            int c = q & 3;
            cp16(sbase + (uint32_t)(t * 128 * RS + r * RS + c * 8) * 2,
                 src + (size_t)r * K + c * 8);
        }
    }
}

__global__ __launch_bounds__(256, 2) void gemm_mma(
    const __half* __restrict__ Ah,
    const __half* __restrict__ Bhi, const __half* __restrict__ Blo,
    float* __restrict__ C, int N, int K)
{
    extern __shared__ __align__(16) __half sm[];

    const int tid  = threadIdx.x;
    const int lane = tid & 31;
    const int wid  = tid >> 5;
    const int wm   = wid & 1;
    const int wn   = wid >> 1;
    const int m0 = blockIdx.y * 128;
    const int n0 = blockIdx.x * 128;

    const __half* srcs[3] = { Ah + (size_t)m0 * K,
                              Bhi + (size_t)n0 * K, Blo + (size_t)n0 * K };

    const int lrow  = (lane & 7) + ((lane >> 3) & 1) * 8;
    const int lkadd = (lane >> 4) * 8;

    const uint32_t sb[2] = { smem_u32(sm), smem_u32(sm + GSTAGE_ELE) };
    const uint32_t aOff   = (uint32_t)((wm * 64 + lrow) * RS + lkadd) * 2;
    const uint32_t bOffHi = TILE_SMB + (uint32_t)((wn * 32 + lrow) * RS + lkadd) * 2;
    const uint32_t bOffLo = bOffHi + TILE_SMB;

    float acc[4][4][4];
#pragma unroll
    for (int i = 0; i < 4; i++)
#pragma unroll
        for (int j = 0; j < 4; j++)
#pragma unroll
            for (int r = 0; r < 4; r++) acc[i][j][r] = 0.0f;

    const int nStages = K >> 5;

    gemm_issue_stage(sb[0], srcs, 0, K, tid);
    CP_COMMIT();

    for (int s = 0; s < nStages; s++) {
        if (s + 1 < nStages) {
            gemm_issue_stage(sb[(s + 1) & 1], srcs, (s + 1) << 5, K, tid);
            CP_COMMIT();
            CP_WAIT(1);
        } else {
            CP_WAIT(0);
        }
        __syncthreads();

        const uint32_t cur = sb[s & 1];
        const uint32_t aBase   = cur + aOff;
        const uint32_t bBaseHi = cur + bOffHi;
        const uint32_t bBaseLo = cur + bOffLo;

#pragma unroll
        for (int ks = 0; ks < 2; ks++) {
            const uint32_t kb = (uint32_t)(ks * 16 * 2);
            uint32_t bH[8], bL[8];
            ldsm4(bH[0], bH[1], bH[2], bH[3], bBaseHi + kb);
            ldsm4(bH[4], bH[5], bH[6], bH[7], bBaseHi + kb + 16 * RS * 2);
            ldsm4(bL[0], bL[1], bL[2], bL[3], bBaseLo + kb);
            ldsm4(bL[4], bL[5], bL[6], bL[7], bBaseLo + kb + 16 * RS * 2);
#pragma unroll
            for (int mt = 0; mt < 4; mt++) {
                uint32_t aH[4];
                const uint32_t moff = (uint32_t)(mt * 16 * RS * 2);
                ldsm4(aH[0], aH[1], aH[2], aH[3], aBase + moff + kb);
#pragma unroll
                for (int nt = 0; nt < 4; nt++) {
                    const int lo = ((nt >> 1) << 2) + (nt & 1);
                    mma16816(acc[mt][nt], aH, bH[lo], bH[lo + 2]);
                    mma16816(acc[mt][nt], aH, bL[lo], bL[lo + 2]);
                }
            }
        }
        __syncthreads();
    }

    const int qrow = lane >> 2;
    const int qcol = (lane & 3) * 2;
#pragma unroll
    for (int mt = 0; mt < 4; mt++) {
#pragma unroll
        for (int nt = 0; nt < 4; nt++) {
            float* base = C + (size_t)(m0 + wm * 64 + mt * 16 + qrow) * N
                            + n0 + wn * 32 + nt * 8 + qcol;
            *(float2*)base = make_float2(acc[mt][nt][0], acc[mt][nt][1]);
            *(float2*)(base + (size_t)8 * N) = make_float2(acc[mt][nt][2], acc[mt][nt][3]);
        }
    }
}

// ---------------------------------------------------------------------------
// RoPE: q in-place (fp32); k -> rope'd fp16 in [b,h,s,dk].
// ---------------------------------------------------------------------------
__global__ __launch_bounds__(256) void rope_split(float* __restrict__ qkv,
                                                  const int* __restrict__ pos,
                                                  __half* __restrict__ khi) {
    int p = blockIdx.x * blockDim.x + threadIdx.x;
    if (p >= BB * SS * HH * (DK / 2)) return;
    int j = p & 31;
    int h = (p >> 5) & (HH - 1);
    int s = (p >> 9) & (SS - 1);
    int b = p >> 20;

    float e   = -(float)(2 * j) / (float)DK;
    float inv = powf(10000.0f, e);
    float ang = (float)pos[s] * inv;
    float sn, cs;
    sincosf(ang, &sn, &cs);

    size_t base = ((size_t)(b * SS + s)) * D3 + h * DK + 2 * j;
    float q1 = qkv[base], q2 = qkv[base + 1];
    qkv[base]     = q1 * cs - q2 * sn;
    qkv[base + 1] = q1 * sn + q2 * cs;

    float k1 = qkv[base + DD], k2 = qkv[base + DD + 1];
    float r1 = k1 * cs - k2 * sn;
    float r2 = k1 * sn + k2 * cs;
    size_t kdst = (((size_t)(b * HH + h) * SS + s)) * DK + 2 * j;
    *(__half2*)(khi + kdst) = __floats2half2_rn(r1, r2);
}

// ---------------------------------------------------------------------------
// V: transpose -> vthi [b,h,dk,S] fp16. Tile 64s x 64d via smem.
// ---------------------------------------------------------------------------
__global__ __launch_bounds__(256) void splitv_t(const float* __restrict__ qkv,
                                                __half* __restrict__ vthi) {
    __shared__ float t[64][65];
    const int tid = threadIdx.x;
    const int s0 = blockIdx.x * 64;
    const int bh = blockIdx.y;
    const int b = bh >> 4, h = bh & 15;

#pragma unroll
    for (int it = 0; it < 4; it++) {
        int idx = it * 256 + tid;
        int sl = idx >> 4;
        int d4 = (idx & 15) * 4;
        float4 v = *(const float4*)(qkv + ((size_t)(b * SS + s0 + sl)) * D3
                                    + 2 * DD + h * DK + d4);
        t[sl][d4 + 0] = v.x; t[sl][d4 + 1] = v.y;
        t[sl][d4 + 2] = v.z; t[sl][d4 + 3] = v.w;
    }
    __syncthreads();

    const int d  = tid >> 2;
    const int sc = (tid & 3) * 16;
    __half hv[16];
#pragma unroll
    for (int j = 0; j < 16; j++)
        hv[j] = __float2half_rn(t[sc + j][d]);
    size_t dst = ((size_t)(b * HH + h) * DK + d) * SS + s0 + sc;
    *(uint4*)(vthi + dst)     = *(uint4*)&hv[0];
    *(uint4*)(vthi + dst + 8) = *(uint4*)&hv[8];
}

// ---------------------------------------------------------------------------
// Tensor-core causal flash attention, pure fp16 operands (single pass per
// GEMM), fp32 accum/softmax. Stage = {Khi, Vthi} each [64][72]; 2 stages,
// cp.async double-buffered. Q has its own smem region (fp16, scaled 1/8).
// Output: fp16 (feeds out-proj A operand).
// ---------------------------------------------------------------------------
#define ARS 72
#define Q_ELE (128 * ARS)                   // 9216 fp16
#define ASTAGE_ELE (2 * 64 * ARS)           // 9216 fp16
#define ATTN_SMEM ((Q_ELE + 2 * ASTAGE_ELE) * 2)   // 55296 B

__device__ __forceinline__ void issue_stage(
    uint32_t sbase, const __half* pKhi, const __half* pVh, int tid)
{
#pragma unroll
    for (int i = 0; i < 4; i++) {
        int chunk = i * 256 + tid;      // 1024 x 16B
        int t   = chunk >> 9;
        int c   = chunk & 511;
        int row = c >> 3, col = c & 7;
        uint32_t dst = sbase + (uint32_t)(t * 64 * ARS + row * ARS + col * 8) * 2;
        const __half* src = (t == 0) ? (pKhi + c * 8)
                                     : (pVh + (size_t)row * SS + col * 8);
        cp16(dst, src);
    }
}

__global__ __launch_bounds__(256) void attn_mma(
    const float* __restrict__ qkv,
    const __half* __restrict__ khi, const __half* __restrict__ vthi,
    __half* __restrict__ ohi)
{
    extern __shared__ __align__(16) __half as_[];
    __half* Qh   = as_;
    __half* buf0 = as_ + Q_ELE;
    __half* buf1 = as_ + Q_ELE + ASTAGE_ELE;

    const int tid  = threadIdx.x;
    const int lane = tid & 31;
    const int wid  = tid >> 5;
    const int qb = blockIdx.x;
    const int h  = blockIdx.y;
    const int b  = blockIdx.z;

    // ---- load Q (scaled 1/8) as fp16 ----
#pragma unroll
    for (int it = 0; it < 8; it++) {
        int idx = it * 256 + tid;
        int r = idx >> 4;
        int c = (idx & 15) * 4;
        const float* src = qkv + ((size_t)(b * SS + qb * 128 + r)) * D3 + h * DK + c;
        float4 v = *(const float4*)src;
        *(__half2*)(Qh + r * ARS + c)     = __floats2half2_rn(v.x * 0.125f, v.y * 0.125f);
        *(__half2*)(Qh + r * ARS + c + 2) = __floats2half2_rn(v.z * 0.125f, v.w * 0.125f);
    }
    __syncthreads();

    // ---- Q fragments in registers ----
    const int lrow  = (lane & 7) + ((lane >> 3) & 1) * 8;
    const int lkadd = (lane >> 4) * 8;
    const uint32_t qBase = smem_u32(Qh) + (uint32_t)((wid * 16 + lrow) * ARS + lkadd) * 2;
    uint32_t qh[4][4];
#pragma unroll
    for (int kc = 0; kc < 4; kc++)
        ldsm4(qh[kc][0], qh[kc][1], qh[kc][2], qh[kc][3], qBase + kc * 32);

    const size_t kvbase = (size_t)(b * HH + h) * SS * DK;
    const __half* pKhi0 = khi  + kvbase;
    const __half* pVh0  = vthi + kvbase;

    const uint32_t sb[2] = { smem_u32(buf0), smem_u32(buf1) };
    const uint32_t fragOff  = (uint32_t)(lrow * ARS + lkadd) * 2;

    float oacc[8][4];
#pragma unroll
    for (int nt = 0; nt < 8; nt++)
#pragma unroll
        for (int r = 0; r < 4; r++) oacc[nt][r] = 0.0f;
    float m0 = -1e30f, m1 = -1e30f, l0 = 0.0f, l1 = 0.0f;

    const int grow0 = qb * 128 + wid * 16 + (lane >> 2);
    const int grow1 = grow0 + 8;
    const int nkt = 2 * qb + 2;

    issue_stage(sb[0], pKhi0, pVh0, tid);
    CP_COMMIT();

    for (int kt = 0; kt < nkt; kt++) {
        if (kt + 1 < nkt) {
            int o = (kt + 1) * 64;
            issue_stage(sb[(kt + 1) & 1], pKhi0 + o * DK, pVh0 + o, tid);
            CP_COMMIT();
            CP_WAIT(1);
        } else {
            CP_WAIT(0);
        }
        __syncthreads();

        const uint32_t cur = sb[kt & 1];
        const uint32_t kBase = cur + fragOff;
        const uint32_t vBase = cur + (uint32_t)(64 * ARS * 2) + fragOff;

        // ---- S = Q K^T (single pass) ----
        float sacc[8][4];
#pragma unroll
        for (int nt = 0; nt < 8; nt++)
#pragma unroll
            for (int r = 0; r < 4; r++) sacc[nt][r] = 0.0f;

#pragma unroll
        for (int kc = 0; kc < 4; kc++) {
            const uint32_t kb = (uint32_t)(kc * 32);
            uint32_t bH[16];
#pragma unroll
            for (int lb = 0; lb < 4; lb++)
                ldsm4(bH[lb * 4 + 0], bH[lb * 4 + 1], bH[lb * 4 + 2], bH[lb * 4 + 3],
                      kBase + kb + (uint32_t)(lb * 16 * ARS * 2));
#pragma unroll
            for (int nt = 0; nt < 8; nt++) {
                const int lo = ((nt >> 1) << 2) + (nt & 1);
                mma16816(sacc[nt], qh[kc], bH[lo], bH[lo + 2]);
            }
        }

        // ---- causal mask ----
        if (kt * 64 + 63 > qb * 128 + wid * 16) {
#pragma unroll
            for (int nt = 0; nt < 8; nt++) {
                int col = kt * 64 + nt * 8 + (lane & 3) * 2;
                if (col > grow0)     sacc[nt][0] = -1e30f;
                if (col + 1 > grow0) sacc[nt][1] = -1e30f;
                if (col > grow1)     sacc[nt][2] = -1e30f;
                if (col + 1 > grow1) sacc[nt][3] = -1e30f;
            }
        }

        // ---- online softmax ----
        float mx0 = -1e30f, mx1 = -1e30f;
#pragma unroll
        for (int nt = 0; nt < 8; nt++) {
            mx0 = fmaxf(mx0, fmaxf(sacc[nt][0], sacc[nt][1]));
            mx1 = fmaxf(mx1, fmaxf(sacc[nt][2], sacc[nt][3]));
        }
        mx0 = fmaxf(mx0, __shfl_xor_sync(0xffffffffu, mx0, 1));
        mx0 = fmaxf(mx0, __shfl_xor_sync(0xffffffffu, mx0, 2));
        mx1 = fmaxf(mx1, __shfl_xor_sync(0xffffffffu, mx1, 1));
        mx1 = fmaxf(mx1, __shfl_xor_sync(0xffffffffu, mx1, 2));
        float mn0 = fmaxf(m0, mx0), mn1 = fmaxf(m1, mx1);
        float cr0 = __expf(m0 - mn0), cr1 = __expf(m1 - mn1);
        float ps0 = 0.0f, ps1 = 0.0f;
#pragma unroll
        for (int nt = 0; nt < 8; nt++) {
            sacc[nt][0] = __expf(sacc[nt][0] - mn0);
            sacc[nt][1] = __expf(sacc[nt][1] - mn0);
            sacc[nt][2] = __expf(sacc[nt][2] - mn1);
            sacc[nt][3] = __expf(sacc[nt][3] - mn1);
            ps0 += sacc[nt][0] + sacc[nt][1];
            ps1 += sacc[nt][2] + sacc[nt][3];
        }
        ps0 += __shfl_xor_sync(0xffffffffu, ps0, 1);
        ps0 += __shfl_xor_sync(0xffffffffu, ps0, 2);
        ps1 += __shfl_xor_sync(0xffffffffu, ps1, 1);
        ps1 += __shfl_xor_sync(0xffffffffu, ps1, 2);
        l0 = l0 * cr0 + ps0;
        l1 = l1 * cr1 + ps1;
        m0 = mn0; m1 = mn1;
#pragma unroll
        for (int nt = 0; nt < 8; nt++) {
            oacc[nt][0] *= cr0; oacc[nt][1] *= cr0;
            oacc[nt][2] *= cr1; oacc[nt][3] *= cr1;
        }

        // ---- O += P V (single pass) ----
#pragma unroll
        for (int kc = 0; kc < 4; kc++) {
            uint32_t aH[4];
            aH[0] = pack_h2(sacc[2*kc][0],   sacc[2*kc][1]);
            aH[1] = pack_h2(sacc[2*kc][2],   sacc[2*kc][3]);
            aH[2] = pack_h2(sacc[2*kc+1][0], sacc[2*kc+1][1]);
            aH[3] = pack_h2(sacc[2*kc+1][2], sacc[2*kc+1][3]);

            const uint32_t kb = (uint32_t)(kc * 32);
            uint32_t vH[16];
#pragma unroll
            for (int lb = 0; lb < 4; lb++)
                ldsm4(vH[lb * 4 + 0], vH[lb * 4 + 1], vH[lb * 4 + 2], vH[lb * 4 + 3],
                      vBase + kb + (uint32_t)(lb * 16 * ARS * 2));
#pragma unroll
            for (int nt = 0; nt < 8; nt++) {
                const int lo = ((nt >> 1) << 2) + (nt & 1);
                mma16816(oacc[nt], aH, vH[lo], vH[lo + 2]);
            }
        }
        __syncthreads();
    }

    // ---- epilogue: write output as fp16 ----
    const float inv0 = 1.0f / l0;
    const float inv1 = 1.0f / l1;
    const int row0 = qb * 128 + wid * 16 + (lane >> 2);
#pragma unroll
    for (int nt = 0; nt < 8; nt++) {
        int col = h * DK + nt * 8 + (lane & 3) * 2;
        size_t d0 = ((size_t)(b * SS + row0)) * DD + col;
        size_t d1 = d0 + (size_t)8 * DD;
        *(__half2*)(ohi + d0) = __floats2half2_rn(oacc[nt][0] * inv0, oacc[nt][1] * inv0);
        *(__half2*)(ohi + d1) = __floats2half2_rn(oacc[nt][2] * inv1, oacc[nt][3] * inv1);
    }
}

// ---------------------------------------------------------------------------
extern "C" void kernel_launch(void* const* d_in, const int* in_sizes, int n_in,
                              void* d_out, int out_size) {
    const float* x    = (const float*)d_in[0];
    const int*   pos  = (const int*)d_in[1];
    const float* Wqkv = (const float*)d_in[2];
    const float* Wo   = (const float*)d_in[3];
    float* out = (float*)d_out;

    float *qkv = nullptr;
    __half *ah, *bhi, *blo, *khi, *vthi;
    cudaGetSymbolAddress((void**)&qkv, g_qkv);
    cudaGetSymbolAddress((void**)&ah,  g_ah);
    cudaGetSymbolAddress((void**)&bhi, g_bhi);
    cudaGetSymbolAddress((void**)&blo, g_blo);
    cudaGetSymbolAddress((void**)&khi, g_khi);
    cudaGetSymbolAddress((void**)&vthi, g_vthi);

    cudaFuncSetAttribute(gemm_mma, cudaFuncAttributeMaxDynamicSharedMemorySize, GEMM_SMEM);
    cudaFuncSetAttribute(attn_mma, cudaFuncAttributeMaxDynamicSharedMemorySize, ATTN_SMEM);

    // 1) cast x to fp16; split Wqkv to fp16 hi/lo
    {
        int n2 = MM * DD / 2;
        cast_fp16<<<(n2 + 255) / 256, 256>>>((const float2*)x, (__half2*)ah, n2);
        int w2 = D3 * DD / 2;
        split_fp16<<<(w2 + 255) / 256, 256>>>((const float2*)Wqkv,
            (__half2*)bhi, (__half2*)blo, w2);
    }

    // 2) QKV projection: [8192,1024] x [3072,1024]^T
    {
        dim3 grid(D3 / 128, MM / 128);
        gemm_mma<<<grid, 256, GEMM_SMEM>>>(ah, bhi, blo, qkv, D3, DD);
    }

    // 3) RoPE (q in place, k -> fp16) + V transpose -> fp16
    {
        int total = BB * SS * HH * (DK / 2);
        rope_split<<<(total + 255) / 256, 256>>>(qkv, pos, khi);
        dim3 gv(SS / 64, BB * HH);
        splitv_t<<<gv, 256>>>(qkv, vthi);
    }

    // 4) Causal flash attention (fp16 single-pass) -> fp16 output into ah
    {
        dim3 grid(SS / 128, HH, BB);
        attn_mma<<<grid, 256, ATTN_SMEM>>>(qkv, khi, vthi, ah);
    }

    // 5) split Wo, then output projection to fp32 out
    {
        int w2 = DD * DD / 2;
        split_fp16<<<(w2 + 255) / 256, 256>>>((const float2*)Wo,
            (__half2*)bhi, (__half2*)blo, w2);
        dim3 grid(DD / 128, MM / 128);
        gemm_mma<<<grid, 256, GEMM_SMEM>>>(ah, bhi, blo, out, DD, DD);
    }
}

// round 16
// speedup vs baseline: 2.5690x; 1.3668x over previous
#include <cuda_runtime.h>
#include <cuda_fp16.h>
#include <cstdint>
#include <cstdio>

// Problem constants
#define BB 4
#define SS 2048
#define DD 1024
#define HH 16
#define DK 64
#define D3 3072
#define MM (BB*SS)          // 8192

// Scratch (device globals: allocation-free contract)
__device__ float g_qkv[(size_t)MM * D3];   // [B*S, 3D] : q | k | v
__device__ __half g_ah [(size_t)MM * DD];  // activations fp16 (x, then attn out)
__device__ __half g_bh [(size_t)D3 * DD];  // weights fp16
__device__ __half g_khi[(size_t)MM * DD];  // [b,h,s,dk]  (rope'd K, fp16)
__device__ __half g_vthi[(size_t)MM * DD]; // [b,h,dk,s]  (V transposed, fp16)

// ---------------------------------------------------------------------------
// helpers
// ---------------------------------------------------------------------------
__device__ __forceinline__ uint32_t smem_u32(const void* p) {
    uint32_t a;
    asm("{ .reg .u64 t; cvta.to.shared.u64 t, %1; cvt.u32.u64 %0, t; }" : "=r"(a) : "l"(p));
    return a;
}
__device__ __forceinline__ void ldsm4(uint32_t& r0, uint32_t& r1, uint32_t& r2,
                                      uint32_t& r3, uint32_t addr) {
    asm volatile("ldmatrix.sync.aligned.m8n8.x4.shared.b16 {%0,%1,%2,%3}, [%4];"
                 : "=r"(r0), "=r"(r1), "=r"(r2), "=r"(r3) : "r"(addr));
}
__device__ __forceinline__ void mma16816(float* c, const uint32_t* a,
                                         uint32_t b0, uint32_t b1) {
    asm volatile(
        "mma.sync.aligned.m16n8k16.row.col.f32.f16.f16.f32 "
        "{%0,%1,%2,%3}, {%4,%5,%6,%7}, {%8,%9}, {%0,%1,%2,%3};"
        : "+f"(c[0]), "+f"(c[1]), "+f"(c[2]), "+f"(c[3])
        : "r"(a[0]), "r"(a[1]), "r"(a[2]), "r"(a[3]), "r"(b0), "r"(b1));
}
__device__ __forceinline__ uint32_t pack_h2(float a, float b) {
    __half2 t = __floats2half2_rn(a, b);
    return *(uint32_t*)&t;
}
__device__ __forceinline__ void cp16(uint32_t dst, const void* src) {
    asm volatile("cp.async.cg.shared.global [%0], [%1], 16;" :: "r"(dst), "l"(src));
}
#define CP_COMMIT() asm volatile("cp.async.commit_group;" ::: "memory")
#define CP_WAIT(n)  asm volatile("cp.async.wait_group %0;" :: "n"(n) : "memory")

// ---------------------------------------------------------------------------
// cast fp32 -> fp16
// ---------------------------------------------------------------------------
__global__ __launch_bounds__(256) void cast_fp16(const float2* __restrict__ x,
                                                 __half2* __restrict__ hi, int n2) {
    int i = blockIdx.x * blockDim.x + threadIdx.x;
    if (i >= n2) return;
    float2 v = x[i];
    hi[i] = __floats2half2_rn(v.x, v.y);
}

// ---------------------------------------------------------------------------
// Warp-MMA fp16 GEMM (NT), cp.async double-buffered, KBLK=32, single pass:
//   C = Ah * Bh^T
// CTA tile 128x128. 8 warps: 2(M) x 4(N), warp tile 64x32.
// smem: 2 stages x 2 tiles x [128][40] fp16 = 40960 B.
// ---------------------------------------------------------------------------
#define RS 40
#define TILE_SMB (128 * RS * 2)             // 10240 B per tile
#define GSTAGE_ELE (2 * 128 * RS)           // fp16 per stage
#define GEMM_SMEM (2 * GSTAGE_ELE * 2)      // 40960 B

__device__ __forceinline__ void gemm_issue_stage(
    uint32_t sbase, const __half* const* srcs, int k0, int K, int tid)
{
#pragma unroll
    for (int t = 0; t < 2; t++) {
        const __half* src = srcs[t] + k0;
#pragma unroll
        for (int it = 0; it < 2; it++) {
            int q = it * 256 + tid;          // 0..511 16B-chunks (128 rows x 4)
            int r = q >> 2;
            int c = q & 3;
            cp16(sbase + (uint32_t)(t * 128 * RS + r * RS + c * 8) * 2,
                 src + (size_t)r * K + c * 8);
        }
    }
}

__global__ __launch_bounds__(256, 2) void gemm_mma(
    const __half* __restrict__ Ah, const __half* __restrict__ Bh,
    float* __restrict__ C, int N, int K)
{
    extern __shared__ __align__(16) __half sm[];

    const int tid  = threadIdx.x;
    const int lane = tid & 31;
    const int wid  = tid >> 5;
    const int wm   = wid & 1;
    const int wn   = wid >> 1;
    const int m0 = blockIdx.y * 128;
    const int n0 = blockIdx.x * 128;

    const __half* srcs[2] = { Ah + (size_t)m0 * K, Bh + (size_t)n0 * K };

    const int lrow  = (lane & 7) + ((lane >> 3) & 1) * 8;
    const int lkadd = (lane >> 4) * 8;

    const uint32_t sb[2] = { smem_u32(sm), smem_u32(sm + GSTAGE_ELE) };
    const uint32_t aOff = (uint32_t)((wm * 64 + lrow) * RS + lkadd) * 2;
    const uint32_t bOff = TILE_SMB + (uint32_t)((wn * 32 + lrow) * RS + lkadd) * 2;

    float acc[4][4][4];
#pragma unroll
    for (int i = 0; i < 4; i++)
#pragma unroll
        for (int j = 0; j < 4; j++)
#pragma unroll
            for (int r = 0; r < 4; r++) acc[i][j][r] = 0.0f;

    const int nStages = K >> 5;

    gemm_issue_stage(sb[0], srcs, 0, K, tid);
    CP_COMMIT();

    for (int s = 0; s < nStages; s++) {
        if (s + 1 < nStages) {
            gemm_issue_stage(sb[(s + 1) & 1], srcs, (s + 1) << 5, K, tid);
            CP_COMMIT();
            CP_WAIT(1);
        } else {
            CP_WAIT(0);
        }
        __syncthreads();

        const uint32_t cur = sb[s & 1];
        const uint32_t aBase = cur + aOff;
        const uint32_t bBase = cur + bOff;

#pragma unroll
        for (int ks = 0; ks < 2; ks++) {
            const uint32_t kb = (uint32_t)(ks * 16 * 2);
            uint32_t bH[8];
            ldsm4(bH[0], bH[1], bH[2], bH[3], bBase + kb);
            ldsm4(bH[4], bH[5], bH[6], bH[7], bBase + kb + 16 * RS * 2);
#pragma unroll
            for (int mt = 0; mt < 4; mt++) {
                uint32_t aH[4];
                const uint32_t moff = (uint32_t)(mt * 16 * RS * 2);
                ldsm4(aH[0], aH[1], aH[2], aH[3], aBase + moff + kb);
#pragma unroll
                for (int nt = 0; nt < 4; nt++) {
                    const int lo = ((nt >> 1) << 2) + (nt & 1);
                    mma16816(acc[mt][nt], aH, bH[lo], bH[lo + 2]);
                }
            }
        }
        __syncthreads();
    }

    const int qrow = lane >> 2;
    const int qcol = (lane & 3) * 2;
#pragma unroll
    for (int mt = 0; mt < 4; mt++) {
#pragma unroll
        for (int nt = 0; nt < 4; nt++) {
            float* base = C + (size_t)(m0 + wm * 64 + mt * 16 + qrow) * N
                            + n0 + wn * 32 + nt * 8 + qcol;
            *(float2*)base = make_float2(acc[mt][nt][0], acc[mt][nt][1]);
            *(float2*)(base + (size_t)8 * N) = make_float2(acc[mt][nt][2], acc[mt][nt][3]);
        }
    }
}

// ---------------------------------------------------------------------------
// RoPE: q in-place (fp32); k -> rope'd fp16 in [b,h,s,dk].
// ---------------------------------------------------------------------------
__global__ __launch_bounds__(256) void rope_split(float* __restrict__ qkv,
                                                  const int* __restrict__ pos,
                                                  __half* __restrict__ khi) {
    int p = blockIdx.x * blockDim.x + threadIdx.x;
    if (p >= BB * SS * HH * (DK / 2)) return;
    int j = p & 31;
    int h = (p >> 5) & (HH - 1);
    int s = (p >> 9) & (SS - 1);
    int b = p >> 20;

    float e   = -(float)(2 * j) / (float)DK;
    float inv = powf(10000.0f, e);
    float ang = (float)pos[s] * inv;
    float sn, cs;
    sincosf(ang, &sn, &cs);

    size_t base = ((size_t)(b * SS + s)) * D3 + h * DK + 2 * j;
    float q1 = qkv[base], q2 = qkv[base + 1];
    qkv[base]     = q1 * cs - q2 * sn;
    qkv[base + 1] = q1 * sn + q2 * cs;

    float k1 = qkv[base + DD], k2 = qkv[base + DD + 1];
    float r1 = k1 * cs - k2 * sn;
    float r2 = k1 * sn + k2 * cs;
    size_t kdst = (((size_t)(b * HH + h) * SS + s)) * DK + 2 * j;
    *(__half2*)(khi + kdst) = __floats2half2_rn(r1, r2);
}

// ---------------------------------------------------------------------------
// V: transpose -> vthi [b,h,dk,S] fp16. Tile 64s x 64d via smem.
// ---------------------------------------------------------------------------
__global__ __launch_bounds__(256) void splitv_t(const float* __restrict__ qkv,
                                                __half* __restrict__ vthi) {
    __shared__ float t[64][65];
    const int tid = threadIdx.x;
    const int s0 = blockIdx.x * 64;
    const int bh = blockIdx.y;
    const int b = bh >> 4, h = bh & 15;

#pragma unroll
    for (int it = 0; it < 4; it++) {
        int idx = it * 256 + tid;
        int sl = idx >> 4;
        int d4 = (idx & 15) * 4;
        float4 v = *(const float4*)(qkv + ((size_t)(b * SS + s0 + sl)) * D3
                                    + 2 * DD + h * DK + d4);
        t[sl][d4 + 0] = v.x; t[sl][d4 + 1] = v.y;
        t[sl][d4 + 2] = v.z; t[sl][d4 + 3] = v.w;
    }
    __syncthreads();

    const int d  = tid >> 2;
    const int sc = (tid & 3) * 16;
    __half hv[16];
#pragma unroll
    for (int j = 0; j < 16; j++)
        hv[j] = __float2half_rn(t[sc + j][d]);
    size_t dst = ((size_t)(b * HH + h) * DK + d) * SS + s0 + sc;
    *(uint4*)(vthi + dst)     = *(uint4*)&hv[0];
    *(uint4*)(vthi + dst + 8) = *(uint4*)&hv[8];
}

// ---------------------------------------------------------------------------
// Tensor-core causal flash attention, pure fp16 operands, fp32 accum/softmax.
// Stage = {Khi, Vthi} each [64][72]; 2 stages, cp.async double-buffered.
// ---------------------------------------------------------------------------
#define ARS 72
#define Q_ELE (128 * ARS)                   // 9216 fp16
#define ASTAGE_ELE (2 * 64 * ARS)           // 9216 fp16
#define ATTN_SMEM ((Q_ELE + 2 * ASTAGE_ELE) * 2)   // 55296 B

__device__ __forceinline__ void issue_stage(
    uint32_t sbase, const __half* pKhi, const __half* pVh, int tid)
{
#pragma unroll
    for (int i = 0; i < 4; i++) {
        int chunk = i * 256 + tid;      // 1024 x 16B
        int t   = chunk >> 9;
        int c   = chunk & 511;
        int row = c >> 3, col = c & 7;
        uint32_t dst = sbase + (uint32_t)(t * 64 * ARS + row * ARS + col * 8) * 2;
        const __half* src = (t == 0) ? (pKhi + c * 8)
                                     : (pVh + (size_t)row * SS + col * 8);
        cp16(dst, src);
    }
}

__global__ __launch_bounds__(256) void attn_mma(
    const float* __restrict__ qkv,
    const __half* __restrict__ khi, const __half* __restrict__ vthi,
    __half* __restrict__ ohi)
{
    extern __shared__ __align__(16) __half as_[];
    __half* Qh   = as_;
    __half* buf0 = as_ + Q_ELE;
    __half* buf1 = as_ + Q_ELE + ASTAGE_ELE;

    const int tid  = threadIdx.x;
    const int lane = tid & 31;
    const int wid  = tid >> 5;
    const int qb = blockIdx.x;
    const int h  = blockIdx.y;
    const int b  = blockIdx.z;

    // ---- load Q (scaled 1/8) as fp16 ----
#pragma unroll
    for (int it = 0; it < 8; it++) {
        int idx = it * 256 + tid;
        int r = idx >> 4;
        int c = (idx & 15) * 4;
        const float* src = qkv + ((size_t)(b * SS + qb * 128 + r)) * D3 + h * DK + c;
        float4 v = *(const float4*)src;
        *(__half2*)(Qh + r * ARS + c)     = __floats2half2_rn(v.x * 0.125f, v.y * 0.125f);
        *(__half2*)(Qh + r * ARS + c + 2) = __floats2half2_rn(v.z * 0.125f, v.w * 0.125f);
    }
    __syncthreads();

    // ---- Q fragments in registers ----
    const int lrow  = (lane & 7) + ((lane >> 3) & 1) * 8;
    const int lkadd = (lane >> 4) * 8;
    const uint32_t qBase = smem_u32(Qh) + (uint32_t)((wid * 16 + lrow) * ARS + lkadd) * 2;
    uint32_t qh[4][4];
#pragma unroll
    for (int kc = 0; kc < 4; kc++)
        ldsm4(qh[kc][0], qh[kc][1], qh[kc][2], qh[kc][3], qBase + kc * 32);

    const size_t kvbase = (size_t)(b * HH + h) * SS * DK;
    const __half* pKhi0 = khi  + kvbase;
    const __half* pVh0  = vthi + kvbase;

    const uint32_t sb[2] = { smem_u32(buf0), smem_u32(buf1) };
    const uint32_t fragOff  = (uint32_t)(lrow * ARS + lkadd) * 2;

    float oacc[8][4];
#pragma unroll
    for (int nt = 0; nt < 8; nt++)
#pragma unroll
        for (int r = 0; r < 4; r++) oacc[nt][r] = 0.0f;
    float m0 = -1e30f, m1 = -1e30f, l0 = 0.0f, l1 = 0.0f;

    const int grow0 = qb * 128 + wid * 16 + (lane >> 2);
    const int grow1 = grow0 + 8;
    const int nkt = 2 * qb + 2;

    issue_stage(sb[0], pKhi0, pVh0, tid);
    CP_COMMIT();

    for (int kt = 0; kt < nkt; kt++) {
        if (kt + 1 < nkt) {
            int o = (kt + 1) * 64;
            issue_stage(sb[(kt + 1) & 1], pKhi0 + o * DK, pVh0 + o, tid);
            CP_COMMIT();
            CP_WAIT(1);
        } else {
            CP_WAIT(0);
        }
        __syncthreads();

        const uint32_t cur = sb[kt & 1];
        const uint32_t kBase = cur + fragOff;
        const uint32_t vBase = cur + (uint32_t)(64 * ARS * 2) + fragOff;

        // ---- S = Q K^T ----
        float sacc[8][4];
#pragma unroll
        for (int nt = 0; nt < 8; nt++)
#pragma unroll
            for (int r = 0; r < 4; r++) sacc[nt][r] = 0.0f;

#pragma unroll
        for (int kc = 0; kc < 4; kc++) {
            const uint32_t kb = (uint32_t)(kc * 32);
            uint32_t bH[16];
#pragma unroll
            for (int lb = 0; lb < 4; lb++)
                ldsm4(bH[lb * 4 + 0], bH[lb * 4 + 1], bH[lb * 4 + 2], bH[lb * 4 + 3],
                      kBase + kb + (uint32_t)(lb * 16 * ARS * 2));
#pragma unroll
            for (int nt = 0; nt < 8; nt++) {
                const int lo = ((nt >> 1) << 2) + (nt & 1);
                mma16816(sacc[nt], qh[kc], bH[lo], bH[lo + 2]);
            }
        }

        // ---- causal mask ----
        if (kt * 64 + 63 > qb * 128 + wid * 16) {
#pragma unroll
            for (int nt = 0; nt < 8; nt++) {
                int col = kt * 64 + nt * 8 + (lane & 3) * 2;
                if (col > grow0)     sacc[nt][0] = -1e30f;
                if (col + 1 > grow0) sacc[nt][1] = -1e30f;
                if (col > grow1)     sacc[nt][2] = -1e30f;
                if (col + 1 > grow1) sacc[nt][3] = -1e30f;
            }
        }

        // ---- online softmax ----
        float mx0 = -1e30f, mx1 = -1e30f;
#pragma unroll
        for (int nt = 0; nt < 8; nt++) {
            mx0 = fmaxf(mx0, fmaxf(sacc[nt][0], sacc[nt][1]));
            mx1 = fmaxf(mx1, fmaxf(sacc[nt][2], sacc[nt][3]));
        }
        mx0 = fmaxf(mx0, __shfl_xor_sync(0xffffffffu, mx0, 1));
        mx0 = fmaxf(mx0, __shfl_xor_sync(0xffffffffu, mx0, 2));
        mx1 = fmaxf(mx1, __shfl_xor_sync(0xffffffffu, mx1, 1));
        mx1 = fmaxf(mx1, __shfl_xor_sync(0xffffffffu, mx1, 2));
        float mn0 = fmaxf(m0, mx0), mn1 = fmaxf(m1, mx1);
        float cr0 = __expf(m0 - mn0), cr1 = __expf(m1 - mn1);
        float ps0 = 0.0f, ps1 = 0.0f;
#pragma unroll
        for (int nt = 0; nt < 8; nt++) {
            sacc[nt][0] = __expf(sacc[nt][0] - mn0);
            sacc[nt][1] = __expf(sacc[nt][1] - mn0);
            sacc[nt][2] = __expf(sacc[nt][2] - mn1);
            sacc[nt][3] = __expf(sacc[nt][3] - mn1);
            ps0 += sacc[nt][0] + sacc[nt][1];
            ps1 += sacc[nt][2] + sacc[nt][3];
        }
        ps0 += __shfl_xor_sync(0xffffffffu, ps0, 1);
        ps0 += __shfl_xor_sync(0xffffffffu, ps0, 2);
        ps1 += __shfl_xor_sync(0xffffffffu, ps1, 1);
        ps1 += __shfl_xor_sync(0xffffffffu, ps1, 2);
        l0 = l0 * cr0 + ps0;
        l1 = l1 * cr1 + ps1;
        m0 = mn0; m1 = mn1;
#pragma unroll
        for (int nt = 0; nt < 8; nt++) {
            oacc[nt][0] *= cr0; oacc[nt][1] *= cr0;
            oacc[nt][2] *= cr1; oacc[nt][3] *= cr1;
        }

        // ---- O += P V ----
#pragma unroll
        for (int kc = 0; kc < 4; kc++) {
            uint32_t aH[4];
            aH[0] = pack_h2(sacc[2*kc][0],   sacc[2*kc][1]);
            aH[1] = pack_h2(sacc[2*kc][2],   sacc[2*kc][3]);
            aH[2] = pack_h2(sacc[2*kc+1][0], sacc[2*kc+1][1]);
            aH[3] = pack_h2(sacc[2*kc+1][2], sacc[2*kc+1][3]);

            const uint32_t kb = (uint32_t)(kc * 32);
            uint32_t vH[16];
#pragma unroll
            for (int lb = 0; lb < 4; lb++)
                ldsm4(vH[lb * 4 + 0], vH[lb * 4 + 1], vH[lb * 4 + 2], vH[lb * 4 + 3],
                      vBase + kb + (uint32_t)(lb * 16 * ARS * 2));
#pragma unroll
            for (int nt = 0; nt < 8; nt++) {
                const int lo = ((nt >> 1) << 2) + (nt & 1);
                mma16816(oacc[nt], aH, vH[lo], vH[lo + 2]);
            }
        }
        __syncthreads();
    }

    // ---- epilogue: write output as fp16 ----
    const float inv0 = 1.0f / l0;
    const float inv1 = 1.0f / l1;
    const int row0 = qb * 128 + wid * 16 + (lane >> 2);
#pragma unroll
    for (int nt = 0; nt < 8; nt++) {
        int col = h * DK + nt * 8 + (lane & 3) * 2;
        size_t d0 = ((size_t)(b * SS + row0)) * DD + col;
        size_t d1 = d0 + (size_t)8 * DD;
        *(__half2*)(ohi + d0) = __floats2half2_rn(oacc[nt][0] * inv0, oacc[nt][1] * inv0);
        *(__half2*)(ohi + d1) = __floats2half2_rn(oacc[nt][2] * inv1, oacc[nt][3] * inv1);
    }
}

// ---------------------------------------------------------------------------
extern "C" void kernel_launch(void* const* d_in, const int* in_sizes, int n_in,
                              void* d_out, int out_size) {
    const float* x    = (const float*)d_in[0];
    const int*   pos  = (const int*)d_in[1];
    const float* Wqkv = (const float*)d_in[2];
    const float* Wo   = (const float*)d_in[3];
    float* out = (float*)d_out;

    float *qkv = nullptr;
    __half *ah, *bh, *khi, *vthi;
    cudaGetSymbolAddress((void**)&qkv, g_qkv);
    cudaGetSymbolAddress((void**)&ah,  g_ah);
    cudaGetSymbolAddress((void**)&bh,  g_bh);
    cudaGetSymbolAddress((void**)&khi, g_khi);
    cudaGetSymbolAddress((void**)&vthi, g_vthi);

    cudaFuncSetAttribute(gemm_mma, cudaFuncAttributeMaxDynamicSharedMemorySize, GEMM_SMEM);
    cudaFuncSetAttribute(attn_mma, cudaFuncAttributeMaxDynamicSharedMemorySize, ATTN_SMEM);

    // 1) cast x and Wqkv to fp16
    {
        int n2 = MM * DD / 2;
        cast_fp16<<<(n2 + 255) / 256, 256>>>((const float2*)x, (__half2*)ah, n2);
        int w2 = D3 * DD / 2;
        cast_fp16<<<(w2 + 255) / 256, 256>>>((const float2*)Wqkv, (__half2*)bh, w2);
    }

    // 2) QKV projection: [8192,1024] x [3072,1024]^T
    {
        dim3 grid(D3 / 128, MM / 128);
        gemm_mma<<<grid, 256, GEMM_SMEM>>>(ah, bh, qkv, D3, DD);
    }

    // 3) RoPE (q in place, k -> fp16) + V transpose -> fp16
    {
        int total = BB * SS * HH * (DK / 2);
        rope_split<<<(total + 255) / 256, 256>>>(qkv, pos, khi);
        dim3 gv(SS / 64, BB * HH);
        splitv_t<<<gv, 256>>>(qkv, vthi);
    }

    // 4) Causal flash attention (fp16 single-pass) -> fp16 output into ah
    {
        dim3 grid(SS / 128, HH, BB);
        attn_mma<<<grid, 256, ATTN_SMEM>>>(qkv, khi, vthi, ah);
    }

    // 5) cast Wo, then output projection to fp32 out
    {
        int w2 = DD * DD / 2;
        cast_fp16<<<(w2 + 255) / 256, 256>>>((const float2*)Wo, (__half2*)bh, w2);
        dim3 grid(DD / 128, MM / 128);
        gemm_mma<<<grid, 256, GEMM_SMEM>>>(ah, bh, out, DD, DD);
    }
}

// round 17
// speedup vs baseline: 2.6132x; 1.0172x over previous
#include <cuda_runtime.h>
#include <cuda_fp16.h>
#include <cstdint>
#include <cstdio>

// Problem constants
#define BB 4
#define SS 2048
#define DD 1024
#define HH 16
#define DK 64
#define D3 3072
#define MM (BB*SS)          // 8192

// Scratch (device globals: allocation-free contract)
__device__ __half g_qkvh[(size_t)MM * D3]; // [B*S, 3D] fp16 : q | k | v
__device__ __half g_ah [(size_t)MM * DD];  // activations fp16 (x, then attn out)
__device__ __half g_bh [(size_t)D3 * DD];  // weights fp16
__device__ __half g_khi[(size_t)MM * DD];  // [b,h,s,dk]  (rope'd K, fp16)
__device__ __half g_vthi[(size_t)MM * DD]; // [b,h,dk,s]  (V transposed, fp16)

// ---------------------------------------------------------------------------
// helpers
// ---------------------------------------------------------------------------
__device__ __forceinline__ uint32_t smem_u32(const void* p) {
    uint32_t a;
    asm("{ .reg .u64 t; cvta.to.shared.u64 t, %1; cvt.u32.u64 %0, t; }" : "=r"(a) : "l"(p));
    return a;
}
__device__ __forceinline__ void ldsm4(uint32_t& r0, uint32_t& r1, uint32_t& r2,
                                      uint32_t& r3, uint32_t addr) {
    asm volatile("ldmatrix.sync.aligned.m8n8.x4.shared.b16 {%0,%1,%2,%3}, [%4];"
                 : "=r"(r0), "=r"(r1), "=r"(r2), "=r"(r3) : "r"(addr));
}
__device__ __forceinline__ void mma16816(float* c, const uint32_t* a,
                                         uint32_t b0, uint32_t b1) {
    asm volatile(
        "mma.sync.aligned.m16n8k16.row.col.f32.f16.f16.f32 "
        "{%0,%1,%2,%3}, {%4,%5,%6,%7}, {%8,%9}, {%0,%1,%2,%3};"
        : "+f"(c[0]), "+f"(c[1]), "+f"(c[2]), "+f"(c[3])
        : "r"(a[0]), "r"(a[1]), "r"(a[2]), "r"(a[3]), "r"(b0), "r"(b1));
}
__device__ __forceinline__ uint32_t pack_h2(float a, float b) {
    __half2 t = __floats2half2_rn(a, b);
    return *(uint32_t*)&t;
}
__device__ __forceinline__ void cp16(uint32_t dst, const void* src) {
    asm volatile("cp.async.cg.shared.global [%0], [%1], 16;" :: "r"(dst), "l"(src));
}
#define CP_COMMIT() asm volatile("cp.async.commit_group;" ::: "memory")
#define CP_WAIT(n)  asm volatile("cp.async.wait_group %0;" :: "n"(n) : "memory")

// typed C-store: fp32 -> float2 / fp16 -> half2
__device__ __forceinline__ void store_c2(float* p, float a, float b) {
    *(float2*)p = make_float2(a, b);
}
__device__ __forceinline__ void store_c2(__half* p, float a, float b) {
    *(__half2*)p = __floats2half2_rn(a, b);
}

// ---------------------------------------------------------------------------
// cast fp32 -> fp16
// ---------------------------------------------------------------------------
__global__ __launch_bounds__(256) void cast_fp16(const float2* __restrict__ x,
                                                 __half2* __restrict__ hi, int n2) {
    int i = blockIdx.x * blockDim.x + threadIdx.x;
    if (i >= n2) return;
    float2 v = x[i];
    hi[i] = __floats2half2_rn(v.x, v.y);
}

// ---------------------------------------------------------------------------
// Warp-MMA fp16 GEMM (NT), cp.async double-buffered, KBLK=32, single pass:
//   C = Ah * Bh^T   (OutT = __half or float)
// CTA tile 128x128. 8 warps: 2(M) x 4(N), warp tile 64x32.
// smem: 2 stages x 2 tiles x [128][40] fp16 = 40960 B.
// ---------------------------------------------------------------------------
#define RS 40
#define TILE_SMB (128 * RS * 2)             // 10240 B per tile
#define GSTAGE_ELE (2 * 128 * RS)           // fp16 per stage
#define GEMM_SMEM (2 * GSTAGE_ELE * 2)      // 40960 B

__device__ __forceinline__ void gemm_issue_stage(
    uint32_t sbase, const __half* const* srcs, int k0, int K, int tid)
{
#pragma unroll
    for (int t = 0; t < 2; t++) {
        const __half* src = srcs[t] + k0;
#pragma unroll
        for (int it = 0; it < 2; it++) {
            int q = it * 256 + tid;          // 0..511 16B-chunks (128 rows x 4)
            int r = q >> 2;
            int c = q & 3;
            cp16(sbase + (uint32_t)(t * 128 * RS + r * RS + c * 8) * 2,
                 src + (size_t)r * K + c * 8);
        }
    }
}

template <typename OutT>
__global__ __launch_bounds__(256, 2) void gemm_mma(
    const __half* __restrict__ Ah, const __half* __restrict__ Bh,
    OutT* __restrict__ C, int N, int K)
{
    extern __shared__ __align__(16) __half sm[];

    const int tid  = threadIdx.x;
    const int lane = tid & 31;
    const int wid  = tid >> 5;
    const int wm   = wid & 1;
    const int wn   = wid >> 1;
    const int m0 = blockIdx.y * 128;
    const int n0 = blockIdx.x * 128;

    const __half* srcs[2] = { Ah + (size_t)m0 * K, Bh + (size_t)n0 * K };

    const int lrow  = (lane & 7) + ((lane >> 3) & 1) * 8;
    const int lkadd = (lane >> 4) * 8;

    const uint32_t sb[2] = { smem_u32(sm), smem_u32(sm + GSTAGE_ELE) };
    const uint32_t aOff = (uint32_t)((wm * 64 + lrow) * RS + lkadd) * 2;
    const uint32_t bOff = TILE_SMB + (uint32_t)((wn * 32 + lrow) * RS + lkadd) * 2;

    float acc[4][4][4];
#pragma unroll
    for (int i = 0; i < 4; i++)
#pragma unroll
        for (int j = 0; j < 4; j++)
#pragma unroll
            for (int r = 0; r < 4; r++) acc[i][j][r] = 0.0f;

    const int nStages = K >> 5;

    gemm_issue_stage(sb[0], srcs, 0, K, tid);
    CP_COMMIT();

    for (int s = 0; s < nStages; s++) {
        if (s + 1 < nStages) {
            gemm_issue_stage(sb[(s + 1) & 1], srcs, (s + 1) << 5, K, tid);
            CP_COMMIT();
            CP_WAIT(1);
        } else {
            CP_WAIT(0);
        }
        __syncthreads();

        const uint32_t cur = sb[s & 1];
        const uint32_t aBase = cur + aOff;
        const uint32_t bBase = cur + bOff;

#pragma unroll
        for (int ks = 0; ks < 2; ks++) {
            const uint32_t kb = (uint32_t)(ks * 16 * 2);
            uint32_t bH[8];
            ldsm4(bH[0], bH[1], bH[2], bH[3], bBase + kb);
            ldsm4(bH[4], bH[5], bH[6], bH[7], bBase + kb + 16 * RS * 2);
#pragma unroll
            for (int mt = 0; mt < 4; mt++) {
                uint32_t aH[4];
                const uint32_t moff = (uint32_t)(mt * 16 * RS * 2);
                ldsm4(aH[0], aH[1], aH[2], aH[3], aBase + moff + kb);
#pragma unroll
                for (int nt = 0; nt < 4; nt++) {
                    const int lo = ((nt >> 1) << 2) + (nt & 1);
                    mma16816(acc[mt][nt], aH, bH[lo], bH[lo + 2]);
                }
            }
        }
        __syncthreads();
    }

    const int qrow = lane >> 2;
    const int qcol = (lane & 3) * 2;
#pragma unroll
    for (int mt = 0; mt < 4; mt++) {
#pragma unroll
        for (int nt = 0; nt < 4; nt++) {
            OutT* base = C + (size_t)(m0 + wm * 64 + mt * 16 + qrow) * N
                           + n0 + wn * 32 + nt * 8 + qcol;
            store_c2(base, acc[mt][nt][0], acc[mt][nt][1]);
            store_c2(base + (size_t)8 * N, acc[mt][nt][2], acc[mt][nt][3]);
        }
    }
}

// ---------------------------------------------------------------------------
// RoPE on fp16 qkv: q in-place (rope + 1/8 scale); k -> khi [b,h,s,dk] fp16.
// ---------------------------------------------------------------------------
__global__ __launch_bounds__(256) void rope_split(__half* __restrict__ qkvh,
                                                  const int* __restrict__ pos,
                                                  __half* __restrict__ khi) {
    int p = blockIdx.x * blockDim.x + threadIdx.x;
    if (p >= BB * SS * HH * (DK / 2)) return;
    int j = p & 31;
    int h = (p >> 5) & (HH - 1);
    int s = (p >> 9) & (SS - 1);
    int b = p >> 20;

    float e   = -(float)(2 * j) / (float)DK;
    float inv = powf(10000.0f, e);
    float ang = (float)pos[s] * inv;
    float sn, cs;
    sincosf(ang, &sn, &cs);

    size_t base = ((size_t)(b * SS + s)) * D3 + h * DK + 2 * j;
    __half2 qp = *(__half2*)(qkvh + base);
    float q1 = __half2float(qp.x), q2 = __half2float(qp.y);
    *(__half2*)(qkvh + base) = __floats2half2_rn(0.125f * (q1 * cs - q2 * sn),
                                                 0.125f * (q1 * sn + q2 * cs));

    __half2 kp = *(__half2*)(qkvh + base + DD);
    float k1 = __half2float(kp.x), k2 = __half2float(kp.y);
    size_t kdst = (((size_t)(b * HH + h) * SS + s)) * DK + 2 * j;
    *(__half2*)(khi + kdst) = __floats2half2_rn(k1 * cs - k2 * sn,
                                                k1 * sn + k2 * cs);
}

// ---------------------------------------------------------------------------
// V: transpose fp16 -> vthi [b,h,dk,S]. Tile 64s x 64d via smem.
// ---------------------------------------------------------------------------
__global__ __launch_bounds__(256) void splitv_t(const __half* __restrict__ qkvh,
                                                __half* __restrict__ vthi) {
    __shared__ __half t[64][72];
    const int tid = threadIdx.x;
    const int s0 = blockIdx.x * 64;
    const int bh = blockIdx.y;
    const int b = bh >> 4, h = bh & 15;

#pragma unroll
    for (int it = 0; it < 2; it++) {
        int idx = it * 256 + tid;        // 512 chunks of 8 halves
        int sl = idx >> 3;
        int d8 = (idx & 7) * 8;
        *(uint4*)&t[sl][d8] =
            *(const uint4*)(qkvh + ((size_t)(b * SS + s0 + sl)) * D3
                            + 2 * DD + h * DK + d8);
    }
    __syncthreads();

    const int d  = tid >> 2;
    const int sc = (tid & 3) * 16;
    __half hv[16];
#pragma unroll
    for (int j = 0; j < 16; j++)
        hv[j] = t[sc + j][d];
    size_t dst = ((size_t)(b * HH + h) * DK + d) * SS + s0 + sc;
    *(uint4*)(vthi + dst)     = *(uint4*)&hv[0];
    *(uint4*)(vthi + dst + 8) = *(uint4*)&hv[8];
}

// ---------------------------------------------------------------------------
// Tensor-core causal flash attention, pure fp16 operands, fp32 accum/softmax.
// Q loaded via cp.async (already fp16 + pre-scaled). Stage = {Khi, Vthi}
// each [64][72]; 2 stages, cp.async double-buffered.
// ---------------------------------------------------------------------------
#define ARS 72
#define Q_ELE (128 * ARS)                   // 9216 fp16
#define ASTAGE_ELE (2 * 64 * ARS)           // 9216 fp16
#define ATTN_SMEM ((Q_ELE + 2 * ASTAGE_ELE) * 2)   // 55296 B

__device__ __forceinline__ void issue_stage(
    uint32_t sbase, const __half* pKhi, const __half* pVh, int tid)
{
#pragma unroll
    for (int i = 0; i < 4; i++) {
        int chunk = i * 256 + tid;      // 1024 x 16B
        int t   = chunk >> 9;
        int c   = chunk & 511;
        int row = c >> 3, col = c & 7;
        uint32_t dst = sbase + (uint32_t)(t * 64 * ARS + row * ARS + col * 8) * 2;
        const __half* src = (t == 0) ? (pKhi + c * 8)
                                     : (pVh + (size_t)row * SS + col * 8);
        cp16(dst, src);
    }
}

__global__ __launch_bounds__(256) void attn_mma(
    const __half* __restrict__ qkvh,
    const __half* __restrict__ khi, const __half* __restrict__ vthi,
    __half* __restrict__ ohi)
{
    extern __shared__ __align__(16) __half as_[];
    __half* Qh   = as_;
    __half* buf0 = as_ + Q_ELE;
    __half* buf1 = as_ + Q_ELE + ASTAGE_ELE;

    const int tid  = threadIdx.x;
    const int lane = tid & 31;
    const int wid  = tid >> 5;
    const int qb = blockIdx.x;
    const int h  = blockIdx.y;
    const int b  = blockIdx.z;

    const uint32_t qSm = smem_u32(Qh);

    // ---- Q via cp.async: 128 rows x 64 fp16 (pre-scaled, pre-cast) ----
#pragma unroll
    for (int i = 0; i < 4; i++) {
        int chunk = i * 256 + tid;      // 1024 x 16B
        int r  = chunk >> 3;
        int c8 = (chunk & 7) * 8;
        cp16(qSm + (uint32_t)(r * ARS + c8) * 2,
             qkvh + ((size_t)(b * SS + qb * 128 + r)) * D3 + h * DK + c8);
    }
    CP_COMMIT();

    const size_t kvbase = (size_t)(b * HH + h) * SS * DK;
    const __half* pKhi0 = khi  + kvbase;
    const __half* pVh0  = vthi + kvbase;

    const uint32_t sb[2] = { smem_u32(buf0), smem_u32(buf1) };

    // prologue: stage 0
    issue_stage(sb[0], pKhi0, pVh0, tid);
    CP_COMMIT();

    // wait for Q group, load Q fragments
    CP_WAIT(1);
    __syncthreads();

    const int lrow  = (lane & 7) + ((lane >> 3) & 1) * 8;
    const int lkadd = (lane >> 4) * 8;
    const uint32_t qBase = qSm + (uint32_t)((wid * 16 + lrow) * ARS + lkadd) * 2;
    uint32_t qh[4][4];
#pragma unroll
    for (int kc = 0; kc < 4; kc++)
        ldsm4(qh[kc][0], qh[kc][1], qh[kc][2], qh[kc][3], qBase + kc * 32);

    const uint32_t fragOff = (uint32_t)(lrow * ARS + lkadd) * 2;

    float oacc[8][4];
#pragma unroll
    for (int nt = 0; nt < 8; nt++)
#pragma unroll
        for (int r = 0; r < 4; r++) oacc[nt][r] = 0.0f;
    float m0 = -1e30f, m1 = -1e30f, l0 = 0.0f, l1 = 0.0f;

    const int grow0 = qb * 128 + wid * 16 + (lane >> 2);
    const int grow1 = grow0 + 8;
    const int nkt = 2 * qb + 2;

    for (int kt = 0; kt < nkt; kt++) {
        if (kt + 1 < nkt) {
            int o = (kt + 1) * 64;
            issue_stage(sb[(kt + 1) & 1], pKhi0 + o * DK, pVh0 + o, tid);
            CP_COMMIT();
            CP_WAIT(1);
        } else {
            CP_WAIT(0);
        }
        __syncthreads();

        const uint32_t cur = sb[kt & 1];
        const uint32_t kBase = cur + fragOff;
        const uint32_t vBase = cur + (uint32_t)(64 * ARS * 2) + fragOff;

        // ---- S = Q K^T ----
        float sacc[8][4];
#pragma unroll
        for (int nt = 0; nt < 8; nt++)
#pragma unroll
            for (int r = 0; r < 4; r++) sacc[nt][r] = 0.0f;

#pragma unroll
        for (int kc = 0; kc < 4; kc++) {
            const uint32_t kb = (uint32_t)(kc * 32);
            uint32_t bH[16];
#pragma unroll
            for (int lb = 0; lb < 4; lb++)
                ldsm4(bH[lb * 4 + 0], bH[lb * 4 + 1], bH[lb * 4 + 2], bH[lb * 4 + 3],
                      kBase + kb + (uint32_t)(lb * 16 * ARS * 2));
#pragma unroll
            for (int nt = 0; nt < 8; nt++) {
                const int lo = ((nt >> 1) << 2) + (nt & 1);
                mma16816(sacc[nt], qh[kc], bH[lo], bH[lo + 2]);
            }
        }

        // ---- causal mask ----
        if (kt * 64 + 63 > qb * 128 + wid * 16) {
#pragma unroll
            for (int nt = 0; nt < 8; nt++) {
                int col = kt * 64 + nt * 8 + (lane & 3) * 2;
                if (col > grow0)     sacc[nt][0] = -1e30f;
                if (col + 1 > grow0) sacc[nt][1] = -1e30f;
                if (col > grow1)     sacc[nt][2] = -1e30f;
                if (col + 1 > grow1) sacc[nt][3] = -1e30f;
            }
        }

        // ---- online softmax ----
        float mx0 = -1e30f, mx1 = -1e30f;
#pragma unroll
        for (int nt = 0; nt < 8; nt++) {
            mx0 = fmaxf(mx0, fmaxf(sacc[nt][0], sacc[nt][1]));
            mx1 = fmaxf(mx1, fmaxf(sacc[nt][2], sacc[nt][3]));
        }
        mx0 = fmaxf(mx0, __shfl_xor_sync(0xffffffffu, mx0, 1));
        mx0 = fmaxf(mx0, __shfl_xor_sync(0xffffffffu, mx0, 2));
        mx1 = fmaxf(mx1, __shfl_xor_sync(0xffffffffu, mx1, 1));
        mx1 = fmaxf(mx1, __shfl_xor_sync(0xffffffffu, mx1, 2));
        float mn0 = fmaxf(m0, mx0), mn1 = fmaxf(m1, mx1);
        float cr0 = __expf(m0 - mn0), cr1 = __expf(m1 - mn1);
        float ps0 = 0.0f, ps1 = 0.0f;
#pragma unroll
        for (int nt = 0; nt < 8; nt++) {
            sacc[nt][0] = __expf(sacc[nt][0] - mn0);
            sacc[nt][1] = __expf(sacc[nt][1] - mn0);
            sacc[nt][2] = __expf(sacc[nt][2] - mn1);
            sacc[nt][3] = __expf(sacc[nt][3] - mn1);
            ps0 += sacc[nt][0] + sacc[nt][1];
            ps1 += sacc[nt][2] + sacc[nt][3];
        }
        ps0 += __shfl_xor_sync(0xffffffffu, ps0, 1);
        ps0 += __shfl_xor_sync(0xffffffffu, ps0, 2);
        ps1 += __shfl_xor_sync(0xffffffffu, ps1, 1);
        ps1 += __shfl_xor_sync(0xffffffffu, ps1, 2);
        l0 = l0 * cr0 + ps0;
        l1 = l1 * cr1 + ps1;
        m0 = mn0; m1 = mn1;
#pragma unroll
        for (int nt = 0; nt < 8; nt++) {
            oacc[nt][0] *= cr0; oacc[nt][1] *= cr0;
            oacc[nt][2] *= cr1; oacc[nt][3] *= cr1;
        }

        // ---- O += P V ----
#pragma unroll
        for (int kc = 0; kc < 4; kc++) {
            uint32_t aH[4];
            aH[0] = pack_h2(sacc[2*kc][0],   sacc[2*kc][1]);
            aH[1] = pack_h2(sacc[2*kc][2],   sacc[2*kc][3]);
            aH[2] = pack_h2(sacc[2*kc+1][0], sacc[2*kc+1][1]);
            aH[3] = pack_h2(sacc[2*kc+1][2], sacc[2*kc+1][3]);

            const uint32_t kb = (uint32_t)(kc * 32);
            uint32_t vH[16];
#pragma unroll
            for (int lb = 0; lb < 4; lb++)
                ldsm4(vH[lb * 4 + 0], vH[lb * 4 + 1], vH[lb * 4 + 2], vH[lb * 4 + 3],
                      vBase + kb + (uint32_t)(lb * 16 * ARS * 2));
#pragma unroll
            for (int nt = 0; nt < 8; nt++) {
                const int lo = ((nt >> 1) << 2) + (nt & 1);
                mma16816(oacc[nt], aH, vH[lo], vH[lo + 2]);
            }
        }
        __syncthreads();
    }

    // ---- epilogue: write output as fp16 ----
    const float inv0 = 1.0f / l0;
    const float inv1 = 1.0f / l1;
    const int row0 = qb * 128 + wid * 16 + (lane >> 2);
#pragma unroll
    for (int nt = 0; nt < 8; nt++) {
        int col = h * DK + nt * 8 + (lane & 3) * 2;
        size_t d0 = ((size_t)(b * SS + row0)) * DD + col;
        size_t d1 = d0 + (size_t)8 * DD;
        *(__half2*)(ohi + d0) = __floats2half2_rn(oacc[nt][0] * inv0, oacc[nt][1] * inv0);
        *(__half2*)(ohi + d1) = __floats2half2_rn(oacc[nt][2] * inv1, oacc[nt][3] * inv1);
    }
}

// ---------------------------------------------------------------------------
extern "C" void kernel_launch(void* const* d_in, const int* in_sizes, int n_in,
                              void* d_out, int out_size) {
    const float* x    = (const float*)d_in[0];
    const int*   pos  = (const int*)d_in[1];
    const float* Wqkv = (const float*)d_in[2];
    const float* Wo   = (const float*)d_in[3];
    float* out = (float*)d_out;

    __half *qkvh, *ah, *bh, *khi, *vthi;
    cudaGetSymbolAddress((void**)&qkvh, g_qkvh);
    cudaGetSymbolAddress((void**)&ah,  g_ah);
    cudaGetSymbolAddress((void**)&bh,  g_bh);
    cudaGetSymbolAddress((void**)&khi, g_khi);
    cudaGetSymbolAddress((void**)&vthi, g_vthi);

    cudaFuncSetAttribute(gemm_mma<__half>,
                         cudaFuncAttributeMaxDynamicSharedMemorySize, GEMM_SMEM);
    cudaFuncSetAttribute(gemm_mma<float>,
                         cudaFuncAttributeMaxDynamicSharedMemorySize, GEMM_SMEM);
    cudaFuncSetAttribute(attn_mma,
                         cudaFuncAttributeMaxDynamicSharedMemorySize, ATTN_SMEM);

    // 1) cast x and Wqkv to fp16
    {
        int n2 = MM * DD / 2;
        cast_fp16<<<(n2 + 255) / 256, 256>>>((const float2*)x, (__half2*)ah, n2);
        int w2 = D3 * DD / 2;
        cast_fp16<<<(w2 + 255) / 256, 256>>>((const float2*)Wqkv, (__half2*)bh, w2);
    }

    // 2) QKV projection -> fp16 qkv
    {
        dim3 grid(D3 / 128, MM / 128);
        gemm_mma<__half><<<grid, 256, GEMM_SMEM>>>(ah, bh, qkvh, D3, DD);
    }

    // 3) RoPE (q in place + 1/8 scale, k -> khi) + V transpose
    {
        int total = BB * SS * HH * (DK / 2);
        rope_split<<<(total + 255) / 256, 256>>>(qkvh, pos, khi);
        dim3 gv(SS / 64, BB * HH);
        splitv_t<<<gv, 256>>>(qkvh, vthi);
    }

    // 4) Causal flash attention -> fp16 output into ah
    {
        dim3 grid(SS / 128, HH, BB);
        attn_mma<<<grid, 256, ATTN_SMEM>>>(qkvh, khi, vthi, ah);
    }

    // 5) cast Wo, then output projection to fp32 out
    {
        int w2 = DD * DD / 2;
        cast_fp16<<<(w2 + 255) / 256, 256>>>((const float2*)Wo, (__half2*)bh, w2);
        dim3 grid(DD / 128, MM / 128);
        gemm_mma<float><<<grid, 256, GEMM_SMEM>>>(ah, bh, out, DD, DD);
    }
}